// round 2
// baseline (speedup 1.0000x reference)
#include <cuda_runtime.h>
#include <math.h>

#define NN 50000
#define DH 64
#define NH 4
#define FF 256      // NH*DH
#define EMAX 400000

// ---------------- scratch (device globals: no runtime allocation) ------------
static __device__ float d_xb[NN*DH];      // BN'd input
static __device__ float d_fs[NN*FF];      // per-relation projected features
static __device__ float d_hacc[NN*FF];    // accumulated heads
static __device__ float d_el[NN*NH];
static __device__ float d_er[NN*NH];
static __device__ float d_mx[NN*NH];      // segment max
static __device__ float d_sm[NN*NH];      // segment sum
static __device__ float d_ebuf[EMAX*NH];  // per-edge score / weight
static __device__ float d_xm[NN*DH];      // head-mean
static __device__ float d_x1[NN*DH];      // layer-1 output
static __device__ float d_rWsum[DH*FF];
static __device__ float d_bsum[FF];
static __device__ float d_colsum[DH];
static __device__ float d_colsq[DH];

// ---------------- helpers ----------------------------------------------------
__device__ __forceinline__ void atomicMaxF(float* addr, float v) {
    if (v >= 0.f) atomicMax((int*)addr, __float_as_int(v));
    else          atomicMin((unsigned int*)addr, __float_as_uint(v));
}

// ---------------- BN ---------------------------------------------------------
__global__ void bn_stats_init() {
    int t = threadIdx.x;
    if (t < DH) { d_colsum[t] = 0.f; d_colsq[t] = 0.f; }
}

__global__ void bn_reduce(const float* __restrict__ x) {
    int col = threadIdx.x & 63;
    int rg  = threadIdx.x >> 6;   // 0..3
    float s = 0.f, q = 0.f;
    for (int i = blockIdx.x*4 + rg; i < NN; i += gridDim.x*4) {
        float v = x[i*DH + col];
        s += v; q += v*v;
    }
    __shared__ float ss[256], sq[256];
    ss[threadIdx.x] = s; sq[threadIdx.x] = q;
    __syncthreads();
    if (threadIdx.x < 64) {
        s = ss[threadIdx.x] + ss[threadIdx.x+64] + ss[threadIdx.x+128] + ss[threadIdx.x+192];
        q = sq[threadIdx.x] + sq[threadIdx.x+64] + sq[threadIdx.x+128] + sq[threadIdx.x+192];
        atomicAdd(&d_colsum[threadIdx.x], s);
        atomicAdd(&d_colsq[threadIdx.x], q);
    }
}

__global__ void bn_apply(const float* __restrict__ x, const float* __restrict__ g,
                         const float* __restrict__ be) {
    int idx = blockIdx.x*blockDim.x + threadIdx.x;
    if (idx >= NN*DH) return;
    int c = idx & 63;
    float mu  = d_colsum[c] * (1.f/NN);
    float var = d_colsq[c] * (1.f/NN) - mu*mu;
    d_xb[idx] = (x[idx] - mu) * rsqrtf(var + 1e-5f) * g[c] + be[c];
}

// ---------------- misc init --------------------------------------------------
__global__ void zero_hacc() {
    int idx = blockIdx.x*blockDim.x + threadIdx.x;
    if (idx < NN*FF) d_hacc[idx] = 0.f;
}

__global__ void init_ms() {
    int idx = blockIdx.x*blockDim.x + threadIdx.x;
    if (idx < NN*NH) { d_mx[idx] = __int_as_float(0xff800000); d_sm[idx] = 0.f; }
}

__global__ void sum_rw(const float* __restrict__ rW, const float* __restrict__ b) {
    int i = blockIdx.x*blockDim.x + threadIdx.x;
    if (i < DH*FF) d_rWsum[i] = rW[i] + rW[DH*FF + i] + rW[2*DH*FF + i];
    if (i < FF)    d_bsum[i]  = b[i] + b[FF + i] + b[2*FF + i];
}

// ---------------- GEMM: C[M,Nn] (+)= A[M,64] @ B[64,Nn] ----------------------
template<bool ACC, bool RELU, bool BIAS>
__global__ void gemm_k64(const float* __restrict__ A, const float* __restrict__ B,
                         float* __restrict__ C, const float* __restrict__ bias,
                         int M, int Nn) {
    __shared__ float As[64][65];
    __shared__ float Bs[64][65];
    int m0 = blockIdx.x * 64, n0 = blockIdx.y * 64;
    int t = threadIdx.x;  // 256 threads

    #pragma unroll
    for (int l = 0; l < 4; l++) {
        int lin = t + l*256;           // float4 index
        int row = lin >> 4, c4 = lin & 15;
        float4 v = make_float4(0.f,0.f,0.f,0.f);
        if (m0 + row < M) v = *(const float4*)&A[(size_t)(m0+row)*64 + c4*4];
        As[row][c4*4+0] = v.x; As[row][c4*4+1] = v.y;
        As[row][c4*4+2] = v.z; As[row][c4*4+3] = v.w;
        float4 w = *(const float4*)&B[(size_t)row*Nn + n0 + c4*4];
        Bs[row][c4*4+0] = w.x; Bs[row][c4*4+1] = w.y;
        Bs[row][c4*4+2] = w.z; Bs[row][c4*4+3] = w.w;
    }
    __syncthreads();

    int ty = t >> 4, tx = t & 15;
    float acc[4][4] = {};
    #pragma unroll
    for (int k = 0; k < 64; k++) {
        float a0 = As[ty*4+0][k], a1 = As[ty*4+1][k];
        float a2 = As[ty*4+2][k], a3 = As[ty*4+3][k];
        float b0 = Bs[k][tx*4+0], b1 = Bs[k][tx*4+1];
        float b2 = Bs[k][tx*4+2], b3 = Bs[k][tx*4+3];
        acc[0][0] += a0*b0; acc[0][1] += a0*b1; acc[0][2] += a0*b2; acc[0][3] += a0*b3;
        acc[1][0] += a1*b0; acc[1][1] += a1*b1; acc[1][2] += a1*b2; acc[1][3] += a1*b3;
        acc[2][0] += a2*b0; acc[2][1] += a2*b1; acc[2][2] += a2*b2; acc[2][3] += a2*b3;
        acc[3][0] += a3*b0; acc[3][1] += a3*b1; acc[3][2] += a3*b2; acc[3][3] += a3*b3;
    }

    #pragma unroll
    for (int i = 0; i < 4; i++) {
        int m = m0 + ty*4 + i;
        if (m >= M) continue;
        #pragma unroll
        for (int j = 0; j < 4; j++) {
            int n = n0 + tx*4 + j;
            float v = acc[i][j];
            if (BIAS) v += bias[n];
            if (ACC)  v += C[(size_t)m*Nn + n];
            if (RELU) v = fmaxf(v, 0.f);
            C[(size_t)m*Nn + n] = v;
        }
    }
}

// ---------------- attention scores el/er -------------------------------------
__global__ void attn_scores(const float* __restrict__ al, const float* __restrict__ ar) {
    int idx = blockIdx.x*blockDim.x + threadIdx.x;  // n*NH + h
    if (idx >= NN*NH) return;
    int h = idx & 3;
    const float4* f = (const float4*)&d_fs[(size_t)idx * 64];
    const float4* a = (const float4*)&al[h*64];
    const float4* b = (const float4*)&ar[h*64];
    float sl = 0.f, sr = 0.f;
    #pragma unroll
    for (int i = 0; i < 16; i++) {
        float4 fv = f[i], av = a[i], bv = b[i];
        sl += fv.x*av.x + fv.y*av.y + fv.z*av.z + fv.w*av.w;
        sr += fv.x*bv.x + fv.y*bv.y + fv.z*bv.z + fv.w*bv.w;
    }
    d_el[idx] = sl; d_er[idx] = sr;
}

// ---------------- edge softmax -----------------------------------------------
__global__ void edge_max(const int* __restrict__ src, const int* __restrict__ dst, int E) {
    int idx = blockIdx.x*blockDim.x + threadIdx.x;
    if (idx >= E*NH) return;
    int e = idx >> 2, h = idx & 3;
    int s = src[e], d = dst[e];
    float v = d_el[s*NH + h] + d_er[d*NH + h];
    v = (v >= 0.f) ? v : 0.2f*v;        // leaky_relu(0.2)
    d_ebuf[idx] = v;
    atomicMaxF(&d_mx[d*NH + h], v);
}

__global__ void edge_sum(const int* __restrict__ dst, int E) {
    int idx = blockIdx.x*blockDim.x + threadIdx.x;
    if (idx >= E*NH) return;
    int e = idx >> 2, h = idx & 3;
    int d = dst[e];
    float a = __expf(d_ebuf[idx] - d_mx[d*NH + h]);
    d_ebuf[idx] = a;
    atomicAdd(&d_sm[d*NH + h], a);
}

__global__ void edge_scatter(const int* __restrict__ src, const int* __restrict__ dst) {
    int e = blockIdx.x;
    int t = threadIdx.x;                 // 256
    int s = src[e], d = dst[e];          // broadcast loads
    __shared__ float alpha[NH];
    if (t < NH) alpha[t] = d_ebuf[e*NH + t] / d_sm[d*NH + t];
    __syncthreads();
    float v = alpha[t >> 6] * d_fs[(size_t)s*FF + t];
    atomicAdd(&d_hacc[(size_t)d*FF + t], v);
}

// ---------------- head mean --------------------------------------------------
__global__ void head_mean() {
    int idx = blockIdx.x*blockDim.x + threadIdx.x;
    if (idx >= NN*DH) return;
    int n = idx >> 6, c = idx & 63;
    const float* h = &d_hacc[(size_t)n*FF];
    d_xm[idx] = 0.25f * (h[c] + h[64+c] + h[128+c] + h[192+c]);
}

// ---------------- launch -----------------------------------------------------
extern "C" void kernel_launch(void* const* d_in, const int* in_sizes, int n_in,
                              void* d_out, int out_size) {
    const float* x0 = (const float*)d_in[0];
    const int* srcs[3] = {(const int*)d_in[1], (const int*)d_in[3], (const int*)d_in[5]};
    const int* dsts[3] = {(const int*)d_in[2], (const int*)d_in[4], (const int*)d_in[6]};
    int Es[3] = { in_sizes[1], in_sizes[3], in_sizes[5] };
    const float* Wl[2]   = {(const float*)d_in[7],  (const float*)d_in[12]};
    const float* all_[2] = {(const float*)d_in[8],  (const float*)d_in[13]};
    const float* arl[2]  = {(const float*)d_in[9],  (const float*)d_in[14]};
    const float* bl[2]   = {(const float*)d_in[10], (const float*)d_in[15]};
    const float* rWl[2]  = {(const float*)d_in[11], (const float*)d_in[16]};
    const float* fcWl[2] = {(const float*)d_in[17], (const float*)d_in[19]};
    const float* fcbl[2] = {(const float*)d_in[18], (const float*)d_in[20]};
    const float* gl[2]   = {(const float*)d_in[21], (const float*)d_in[23]};
    const float* bel[2]  = {(const float*)d_in[22], (const float*)d_in[24]};

    float *p_xb, *p_fs, *p_hacc, *p_xm, *p_x1, *p_rWsum, *p_bsum;
    cudaGetSymbolAddress((void**)&p_xb,    d_xb);
    cudaGetSymbolAddress((void**)&p_fs,    d_fs);
    cudaGetSymbolAddress((void**)&p_hacc,  d_hacc);
    cudaGetSymbolAddress((void**)&p_xm,    d_xm);
    cudaGetSymbolAddress((void**)&p_x1,    d_x1);
    cudaGetSymbolAddress((void**)&p_rWsum, d_rWsum);
    cudaGetSymbolAddress((void**)&p_bsum,  d_bsum);

    const int TPB = 256;
    dim3 gg((NN+63)/64, 4);     // fs / residual GEMMs (Nn=256)
    dim3 gg_fc((NN+63)/64, 1);  // fc GEMM (Nn=64)

    for (int L = 0; L < 2; L++) {
        const float* xin = (L == 0) ? x0 : p_x1;
        float* xout = (L == 0) ? p_x1 : (float*)d_out;

        bn_stats_init<<<1, 64>>>();
        bn_reduce<<<256, 256>>>(xin);
        bn_apply<<<(NN*DH + TPB-1)/TPB, TPB>>>(xin, gl[L], bel[L]);
        zero_hacc<<<(NN*FF + TPB-1)/TPB, TPB>>>();
        sum_rw<<<(DH*FF + TPB-1)/TPB, TPB>>>(rWl[L], bl[L]);

        for (int r = 0; r < 3; r++) {
            gemm_k64<false,false,false><<<gg, 256>>>(p_xb, Wl[L] + r*DH*FF, p_fs,
                                                     nullptr, NN, FF);
            attn_scores<<<(NN*NH + TPB-1)/TPB, TPB>>>(all_[L] + r*NH*DH, arl[L] + r*NH*DH);
            init_ms<<<(NN*NH + TPB-1)/TPB, TPB>>>();
            int E = Es[r];
            edge_max<<<(E*NH + TPB-1)/TPB, TPB>>>(srcs[r], dsts[r], E);
            edge_sum<<<(E*NH + TPB-1)/TPB, TPB>>>(dsts[r], E);
            edge_scatter<<<E, 256>>>(srcs[r], dsts[r]);
        }

        // residual:  hacc += xb @ (sum_r rW_r) + sum_r b_r
        gemm_k64<true,false,true><<<gg, 256>>>(p_xb, p_rWsum, p_hacc, p_bsum, NN, FF);
        head_mean<<<(NN*DH + TPB-1)/TPB, TPB>>>();
        // fc + relu
        gemm_k64<false,true,true><<<gg_fc, 256>>>(p_xm, fcWl[L], xout, fcbl[L], NN, DH);
    }
}

// round 4
// speedup vs baseline: 1.9040x; 1.9040x over previous
#include <cuda_runtime.h>
#include <math.h>

#define NN 50000
#define DH 64
#define NH 4
#define FF 256      // NH*DH
#define EMAX 400000

// ---------------- scratch (device globals: no runtime allocation) ------------
static __device__ float d_xb[NN*DH];      // BN'd input
static __device__ float d_fs[NN*FF];      // per-relation projected features
static __device__ float d_hacc[NN*FF];    // accumulated heads (init by residual GEMM)
static __device__ float d_el[NN*NH];
static __device__ float d_er[NN*NH];
static __device__ float d_sm[NN*NH];      // segment sum of exp
static __device__ float d_ebuf[EMAX*NH];  // per-edge exp score
static __device__ float d_xm[NN*DH];      // head-mean
static __device__ float d_x1[NN*DH];      // layer-1 output
static __device__ float d_rWsum[DH*FF];
static __device__ float d_bsum[FF];
static __device__ float d_colsum[DH];
static __device__ float d_colsq[DH];

// ---------------- vector reduction helper ------------------------------------
__device__ __forceinline__ void redAdd4(float* addr, float4 v) {
    asm volatile("red.global.add.v4.f32 [%0], {%1,%2,%3,%4};"
                 :: "l"(addr), "f"(v.x), "f"(v.y), "f"(v.z), "f"(v.w) : "memory");
}

// ---------------- BN ---------------------------------------------------------
__global__ void bn_stats_init() {
    int t = threadIdx.x;
    if (t < DH) { d_colsum[t] = 0.f; d_colsq[t] = 0.f; }
}

__global__ void bn_reduce(const float* __restrict__ x) {
    int col = threadIdx.x & 63;
    int rg  = threadIdx.x >> 6;   // 0..3
    float s = 0.f, q = 0.f;
    for (int i = blockIdx.x*4 + rg; i < NN; i += gridDim.x*4) {
        float v = x[i*DH + col];
        s += v; q += v*v;
    }
    __shared__ float ss[256], sq[256];
    ss[threadIdx.x] = s; sq[threadIdx.x] = q;
    __syncthreads();
    if (threadIdx.x < 64) {
        s = ss[threadIdx.x] + ss[threadIdx.x+64] + ss[threadIdx.x+128] + ss[threadIdx.x+192];
        q = sq[threadIdx.x] + sq[threadIdx.x+64] + sq[threadIdx.x+128] + sq[threadIdx.x+192];
        atomicAdd(&d_colsum[threadIdx.x], s);
        atomicAdd(&d_colsq[threadIdx.x], q);
    }
}

__global__ void bn_apply(const float* __restrict__ x, const float* __restrict__ g,
                         const float* __restrict__ be) {
    int idx = blockIdx.x*blockDim.x + threadIdx.x;
    if (idx >= NN*DH) return;
    int c = idx & 63;
    float mu  = d_colsum[c] * (1.f/NN);
    float var = d_colsq[c] * (1.f/NN) - mu*mu;
    d_xb[idx] = (x[idx] - mu) * rsqrtf(var + 1e-5f) * g[c] + be[c];
}

// ---------------- misc init --------------------------------------------------
__global__ void sum_rw(const float* __restrict__ rW, const float* __restrict__ b) {
    int i = blockIdx.x*blockDim.x + threadIdx.x;
    if (i < DH*FF) d_rWsum[i] = rW[i] + rW[DH*FF + i] + rW[2*DH*FF + i];
    if (i < FF)    d_bsum[i]  = b[i] + b[FF + i] + b[2*FF + i];
}

// ---------------- GEMM: C[M,Nn] = A[M,64] @ B[64,Nn] -------------------------
template<bool RELU, bool BIAS>
__global__ void gemm_k64(const float* __restrict__ A, const float* __restrict__ B,
                         float* __restrict__ C, const float* __restrict__ bias,
                         int M, int Nn) {
    __shared__ float As[64][65];
    __shared__ float Bs[64][65];
    int m0 = blockIdx.x * 64, n0 = blockIdx.y * 64;
    int t = threadIdx.x;  // 256 threads

    #pragma unroll
    for (int l = 0; l < 4; l++) {
        int lin = t + l*256;           // float4 index
        int row = lin >> 4, c4 = lin & 15;
        float4 v = make_float4(0.f,0.f,0.f,0.f);
        if (m0 + row < M) v = *(const float4*)&A[(size_t)(m0+row)*64 + c4*4];
        As[row][c4*4+0] = v.x; As[row][c4*4+1] = v.y;
        As[row][c4*4+2] = v.z; As[row][c4*4+3] = v.w;
        float4 w = *(const float4*)&B[(size_t)row*Nn + n0 + c4*4];
        Bs[row][c4*4+0] = w.x; Bs[row][c4*4+1] = w.y;
        Bs[row][c4*4+2] = w.z; Bs[row][c4*4+3] = w.w;
    }
    __syncthreads();

    int ty = t >> 4, tx = t & 15;
    float acc[4][4] = {};
    #pragma unroll
    for (int k = 0; k < 64; k++) {
        float a0 = As[ty*4+0][k], a1 = As[ty*4+1][k];
        float a2 = As[ty*4+2][k], a3 = As[ty*4+3][k];
        float b0 = Bs[k][tx*4+0], b1 = Bs[k][tx*4+1];
        float b2 = Bs[k][tx*4+2], b3 = Bs[k][tx*4+3];
        acc[0][0] += a0*b0; acc[0][1] += a0*b1; acc[0][2] += a0*b2; acc[0][3] += a0*b3;
        acc[1][0] += a1*b0; acc[1][1] += a1*b1; acc[1][2] += a1*b2; acc[1][3] += a1*b3;
        acc[2][0] += a2*b0; acc[2][1] += a2*b1; acc[2][2] += a2*b2; acc[2][3] += a2*b3;
        acc[3][0] += a3*b0; acc[3][1] += a3*b1; acc[3][2] += a3*b2; acc[3][3] += a3*b3;
    }

    #pragma unroll
    for (int i = 0; i < 4; i++) {
        int m = m0 + ty*4 + i;
        if (m >= M) continue;
        #pragma unroll
        for (int j = 0; j < 4; j++) {
            int n = n0 + tx*4 + j;
            float v = acc[i][j];
            if (BIAS) v += bias[n];
            if (RELU) v = fmaxf(v, 0.f);
            C[(size_t)m*Nn + n] = v;
        }
    }
}

// ---------------- attention scores el/er (+ zero sm) -------------------------
__global__ void attn_scores(const float* __restrict__ al, const float* __restrict__ ar) {
    int idx = blockIdx.x*blockDim.x + threadIdx.x;  // n*NH + h
    if (idx >= NN*NH) return;
    int h = idx & 3;
    const float4* f = (const float4*)&d_fs[(size_t)idx * 64];
    const float4* a = (const float4*)&al[h*64];
    const float4* b = (const float4*)&ar[h*64];
    float sl = 0.f, sr = 0.f;
    #pragma unroll
    for (int i = 0; i < 16; i++) {
        float4 fv = f[i], av = a[i], bv = b[i];
        sl += fv.x*av.x + fv.y*av.y + fv.z*av.z + fv.w*av.w;
        sr += fv.x*bv.x + fv.y*bv.y + fv.z*bv.z + fv.w*bv.w;
    }
    d_el[idx] = sl; d_er[idx] = sr;
    d_sm[idx] = 0.f;
}

// ---------------- edge pass 1: exp(leaky(el+er)), accumulate segment sums ----
__global__ void edge_exp(const int* __restrict__ src, const int* __restrict__ dst, int E) {
    int e = blockIdx.x*blockDim.x + threadIdx.x;
    if (e >= E) return;
    int s = src[e], d = dst[e];
    float4 l = *(const float4*)&d_el[s*NH];
    float4 r = *(const float4*)&d_er[d*NH];
    float4 v;
    v.x = l.x + r.x; v.y = l.y + r.y; v.z = l.z + r.z; v.w = l.w + r.w;
    v.x = (v.x >= 0.f) ? v.x : 0.2f*v.x;
    v.y = (v.y >= 0.f) ? v.y : 0.2f*v.y;
    v.z = (v.z >= 0.f) ? v.z : 0.2f*v.z;
    v.w = (v.w >= 0.f) ? v.w : 0.2f*v.w;
    v.x = __expf(v.x); v.y = __expf(v.y); v.z = __expf(v.z); v.w = __expf(v.w);
    *(float4*)&d_ebuf[e*NH] = v;
    redAdd4(&d_sm[d*NH], v);
}

// ---------------- edge pass 2: warp-per-edge weighted scatter -----------------
__global__ void edge_scatter(const int* __restrict__ src, const int* __restrict__ dst, int E) {
    int gw = (blockIdx.x*blockDim.x + threadIdx.x) >> 5;   // global warp id = edge
    int lane = threadIdx.x & 31;
    if (gw >= E) return;
    int s = src[gw], d = dst[gw];          // broadcast loads within warp
    float a = 0.f;
    if (lane < NH) a = d_ebuf[gw*NH + lane] * __frcp_rn(d_sm[d*NH + lane]);
    float alpha = __shfl_sync(0xffffffffu, a, lane >> 3);  // head = lane/8
    int c = lane * 8;
    const float4* fp = (const float4*)&d_fs[(size_t)s*FF + c];
    float4 v0 = fp[0], v1 = fp[1];
    v0.x *= alpha; v0.y *= alpha; v0.z *= alpha; v0.w *= alpha;
    v1.x *= alpha; v1.y *= alpha; v1.z *= alpha; v1.w *= alpha;
    float* hp = &d_hacc[(size_t)d*FF + c];
    redAdd4(hp, v0);
    redAdd4(hp + 4, v1);
}

// ---------------- head mean --------------------------------------------------
__global__ void head_mean() {
    int idx = blockIdx.x*blockDim.x + threadIdx.x;
    if (idx >= NN*DH) return;
    int n = idx >> 6, c = idx & 63;
    const float* h = &d_hacc[(size_t)n*FF];
    d_xm[idx] = 0.25f * (h[c] + h[64+c] + h[128+c] + h[192+c]);
}

// ---------------- launch -----------------------------------------------------
extern "C" void kernel_launch(void* const* d_in, const int* in_sizes, int n_in,
                              void* d_out, int out_size) {
    const float* x0 = (const float*)d_in[0];
    const int* srcs[3] = {(const int*)d_in[1], (const int*)d_in[3], (const int*)d_in[5]};
    const int* dsts[3] = {(const int*)d_in[2], (const int*)d_in[4], (const int*)d_in[6]};
    int Es[3] = { in_sizes[1], in_sizes[3], in_sizes[5] };
    const float* Wl[2]   = {(const float*)d_in[7],  (const float*)d_in[12]};
    const float* all_[2] = {(const float*)d_in[8],  (const float*)d_in[13]};
    const float* arl[2]  = {(const float*)d_in[9],  (const float*)d_in[14]};
    const float* bl[2]   = {(const float*)d_in[10], (const float*)d_in[15]};
    const float* rWl[2]  = {(const float*)d_in[11], (const float*)d_in[16]};
    const float* fcWl[2] = {(const float*)d_in[17], (const float*)d_in[19]};
    const float* fcbl[2] = {(const float*)d_in[18], (const float*)d_in[20]};
    const float* gl[2]   = {(const float*)d_in[21], (const float*)d_in[23]};
    const float* bel[2]  = {(const float*)d_in[22], (const float*)d_in[24]};

    float *p_xb, *p_fs, *p_hacc, *p_xm, *p_x1, *p_rWsum, *p_bsum;
    cudaGetSymbolAddress((void**)&p_xb,    d_xb);
    cudaGetSymbolAddress((void**)&p_fs,    d_fs);
    cudaGetSymbolAddress((void**)&p_hacc,  d_hacc);
    cudaGetSymbolAddress((void**)&p_xm,    d_xm);
    cudaGetSymbolAddress((void**)&p_x1,    d_x1);
    cudaGetSymbolAddress((void**)&p_rWsum, d_rWsum);
    cudaGetSymbolAddress((void**)&p_bsum,  d_bsum);

    const int TPB = 256;
    dim3 gg((NN+63)/64, 4);     // fs / residual GEMMs (Nn=256)
    dim3 gg_fc((NN+63)/64, 1);  // fc GEMM (Nn=64)

    for (int L = 0; L < 2; L++) {
        const float* xin = (L == 0) ? x0 : p_x1;
        float* xout = (L == 0) ? p_x1 : (float*)d_out;

        bn_stats_init<<<1, 64>>>();
        bn_reduce<<<256, 256>>>(xin);
        bn_apply<<<(NN*DH + TPB-1)/TPB, TPB>>>(xin, gl[L], bel[L]);
        sum_rw<<<(DH*FF + TPB-1)/TPB, TPB>>>(rWl[L], bl[L]);

        // residual first: hacc = xb @ (sum_r rW_r) + sum_r b_r  (no zeroing pass)
        gemm_k64<false,true><<<gg, 256>>>(p_xb, p_rWsum, p_hacc, p_bsum, NN, FF);

        for (int r = 0; r < 3; r++) {
            gemm_k64<false,false><<<gg, 256>>>(p_xb, Wl[L] + r*DH*FF, p_fs,
                                               nullptr, NN, FF);
            attn_scores<<<(NN*NH + TPB-1)/TPB, TPB>>>(all_[L] + r*NH*DH, arl[L] + r*NH*DH);
            int E = Es[r];
            edge_exp<<<(E + TPB-1)/TPB, TPB>>>(srcs[r], dsts[r], E);
            edge_scatter<<<(E*32 + TPB-1)/TPB, TPB>>>(srcs[r], dsts[r], E);
        }

        head_mean<<<(NN*DH + TPB-1)/TPB, TPB>>>();
        // fc + relu
        gemm_k64<true,true><<<gg_fc, 256>>>(p_xm, fcWl[L], xout, fcbl[L], NN, DH);
    }
}

// round 5
// speedup vs baseline: 2.6001x; 1.3656x over previous
#include <cuda_runtime.h>
#include <math.h>

#define NN 50000
#define DH 64
#define NH 4
#define FF 256      // NH*DH
#define EMAX 400000

// ---------------- scratch (device globals) -----------------------------------
static __device__ float d_xb[NN*DH];       // BN'd input
static __device__ float d_fs[NN*FF];       // current relation's projected features
static __device__ float d_el[NN*NH];
static __device__ float d_er[NN*NH];
static __device__ float d_xm[NN*DH];       // residual + aggregated head-mean
static __device__ float d_x1[NN*DH];       // layer-1 output
static __device__ float d_rWfold[DH*DH];
static __device__ float d_bfold[DH];
static __device__ float d_Walr[3*DH*8];    // per relation: [64][8] (el cols 0-3, er 4-7)
static __device__ float d_colsum[DH];
static __device__ float d_colsq[DH];
// CSR
static __device__ int d_cnt[NN];
static __device__ int d_cur[NN];
static __device__ int d_off[3*(NN+1)];
static __device__ int d_csrsrc[3*EMAX];

// ---------------- BN ---------------------------------------------------------
__global__ void bn_stats_init() {
    int t = threadIdx.x;
    if (t < DH) { d_colsum[t] = 0.f; d_colsq[t] = 0.f; }
}

__global__ void bn_reduce(const float* __restrict__ x) {
    int col = threadIdx.x & 63;
    int rg  = threadIdx.x >> 6;
    float s = 0.f, q = 0.f;
    for (int i = blockIdx.x*4 + rg; i < NN; i += gridDim.x*4) {
        float v = x[i*DH + col];
        s += v; q += v*v;
    }
    __shared__ float ss[256], sq[256];
    ss[threadIdx.x] = s; sq[threadIdx.x] = q;
    __syncthreads();
    if (threadIdx.x < 64) {
        s = ss[threadIdx.x] + ss[threadIdx.x+64] + ss[threadIdx.x+128] + ss[threadIdx.x+192];
        q = sq[threadIdx.x] + sq[threadIdx.x+64] + sq[threadIdx.x+128] + sq[threadIdx.x+192];
        atomicAdd(&d_colsum[threadIdx.x], s);
        atomicAdd(&d_colsq[threadIdx.x], q);
    }
}

__global__ void bn_apply(const float* __restrict__ x, const float* __restrict__ g,
                         const float* __restrict__ be) {
    int idx = blockIdx.x*blockDim.x + threadIdx.x;
    if (idx >= NN*DH) return;
    int c = idx & 63;
    float mu  = d_colsum[c] * (1.f/NN);
    float var = d_colsq[c] * (1.f/NN) - mu*mu;
    d_xb[idx] = (x[idx] - mu) * rsqrtf(var + 1e-5f) * g[c] + be[c];
}

// ---------------- parameter folding ------------------------------------------
// rWfold[k][c] = 0.25 * sum_r sum_h rW[r][k][h*64+c]; bfold likewise
__global__ void prep_rwfold(const float* __restrict__ rW, const float* __restrict__ b) {
    int idx = blockIdx.x*blockDim.x + threadIdx.x;
    if (idx < DH*DH) {
        int k = idx >> 6, c = idx & 63;
        float s = 0.f;
        #pragma unroll
        for (int r = 0; r < 3; r++)
            #pragma unroll
            for (int h = 0; h < NH; h++)
                s += rW[((size_t)r*DH + k)*FF + h*DH + c];
        d_rWfold[idx] = 0.25f * s;
    }
    if (idx < DH) {
        float s = 0.f;
        #pragma unroll
        for (int r = 0; r < 3; r++)
            #pragma unroll
            for (int h = 0; h < NH; h++)
                s += b[r*FF + h*DH + idx];
        d_bfold[idx] = 0.25f * s;
    }
}

// Walr[r][k][c] = sum_d W[r][k][h*64+d] * (c<4 ? al : ar)[r][h][d],  h = c&3
__global__ void prep_walr(const float* __restrict__ W, const float* __restrict__ al,
                          const float* __restrict__ ar) {
    int idx = blockIdx.x*blockDim.x + threadIdx.x;
    if (idx >= 3*DH*8) return;
    int r = idx / (DH*8);
    int k = (idx >> 3) % DH;
    int c = idx & 7;
    int h = c & 3;
    const float* a = ((c < 4) ? al : ar) + ((size_t)r*NH + h)*DH;
    const float* w = W + ((size_t)r*DH + k)*FF + h*DH;
    float s = 0.f;
    #pragma unroll
    for (int d = 0; d < DH; d++) s += w[d]*a[d];
    d_Walr[idx] = s;
}

// ---------------- CSR build ---------------------------------------------------
__global__ void csr_zero() {
    int i = blockIdx.x*blockDim.x + threadIdx.x;
    if (i < NN) d_cnt[i] = 0;
}

__global__ void csr_hist(const int* __restrict__ dst, int E) {
    int e = blockIdx.x*blockDim.x + threadIdx.x;
    if (e < E) atomicAdd(&d_cnt[dst[e]], 1);
}

__global__ void csr_scan(int* __restrict__ off) {   // single block, 1024 threads
    __shared__ int buf[1024];
    __shared__ int carry;
    int t = threadIdx.x;
    if (t == 0) carry = 0;
    __syncthreads();
    for (int base = 0; base < NN; base += 1024) {
        int v = (base + t < NN) ? d_cnt[base + t] : 0;
        buf[t] = v;
        __syncthreads();
        #pragma unroll
        for (int s2 = 1; s2 < 1024; s2 <<= 1) {
            int x = (t >= s2) ? buf[t - s2] : 0;
            __syncthreads();
            buf[t] += x;
            __syncthreads();
        }
        int excl = buf[t] - v;
        if (base + t < NN) {
            off[base + t]   = carry + excl;
            d_cur[base + t] = carry + excl;
        }
        __syncthreads();
        if (t == 1023) carry += buf[1023];
        __syncthreads();
    }
    if (t == 0) off[NN] = carry;
}

__global__ void csr_fill(const int* __restrict__ src, const int* __restrict__ dst,
                         int* __restrict__ csrc, int E) {
    int e = blockIdx.x*blockDim.x + threadIdx.x;
    if (e >= E) return;
    int pos = atomicAdd(&d_cur[dst[e]], 1);
    csrc[pos] = src[e];
}

// ---------------- GEMM: C[M,Nn] = A[M,64] @ B[64,Nn] -------------------------
template<bool RELU, bool BIAS>
__global__ void gemm_k64(const float* __restrict__ A, const float* __restrict__ B,
                         float* __restrict__ C, const float* __restrict__ bias,
                         int M, int Nn) {
    __shared__ float As[64][65];
    __shared__ float Bs[64][65];
    int m0 = blockIdx.x * 64, n0 = blockIdx.y * 64;
    int t = threadIdx.x;

    #pragma unroll
    for (int l = 0; l < 4; l++) {
        int lin = t + l*256;
        int row = lin >> 4, c4 = lin & 15;
        float4 v = make_float4(0.f,0.f,0.f,0.f);
        if (m0 + row < M) v = *(const float4*)&A[(size_t)(m0+row)*64 + c4*4];
        As[row][c4*4+0] = v.x; As[row][c4*4+1] = v.y;
        As[row][c4*4+2] = v.z; As[row][c4*4+3] = v.w;
        float4 w = *(const float4*)&B[(size_t)row*Nn + n0 + c4*4];
        Bs[row][c4*4+0] = w.x; Bs[row][c4*4+1] = w.y;
        Bs[row][c4*4+2] = w.z; Bs[row][c4*4+3] = w.w;
    }
    __syncthreads();

    int ty = t >> 4, tx = t & 15;
    float acc[4][4] = {};
    #pragma unroll
    for (int k = 0; k < 64; k++) {
        float a0 = As[ty*4+0][k], a1 = As[ty*4+1][k];
        float a2 = As[ty*4+2][k], a3 = As[ty*4+3][k];
        float b0 = Bs[k][tx*4+0], b1 = Bs[k][tx*4+1];
        float b2 = Bs[k][tx*4+2], b3 = Bs[k][tx*4+3];
        acc[0][0] += a0*b0; acc[0][1] += a0*b1; acc[0][2] += a0*b2; acc[0][3] += a0*b3;
        acc[1][0] += a1*b0; acc[1][1] += a1*b1; acc[1][2] += a1*b2; acc[1][3] += a1*b3;
        acc[2][0] += a2*b0; acc[2][1] += a2*b1; acc[2][2] += a2*b2; acc[2][3] += a2*b3;
        acc[3][0] += a3*b0; acc[3][1] += a3*b1; acc[3][2] += a3*b2; acc[3][3] += a3*b3;
    }

    #pragma unroll
    for (int i = 0; i < 4; i++) {
        int m = m0 + ty*4 + i;
        if (m >= M) continue;
        #pragma unroll
        for (int j = 0; j < 4; j++) {
            int n = n0 + tx*4 + j;
            float v = acc[i][j];
            if (BIAS) v += bias[n];
            if (RELU) v = fmaxf(v, 0.f);
            C[(size_t)m*Nn + n] = v;
        }
    }
}

// ---------------- el/er via small GEMM: [el|er] = xb @ Walr ------------------
__global__ void elr_gemm(const float* __restrict__ Walr) {
    __shared__ float sW[DH*8];
    __shared__ float sx[32*68];        // 32 rows, padded stride 68
    int t = threadIdx.x;               // 256
    if (t < 128) ((float4*)sW)[t] = ((const float4*)Walr)[t];
    int n0 = blockIdx.x * 32;
    for (int i = t; i < 512; i += 256) {   // 512 float4 = 32 rows x 16
        int row = i >> 4, c4 = i & 15;
        float4 v = make_float4(0.f,0.f,0.f,0.f);
        if (n0 + row < NN) v = ((const float4*)&d_xb[(size_t)(n0+row)*DH])[c4];
        ((float4*)&sx[row*68])[c4] = v;
    }
    __syncthreads();
    int row = t >> 3, c = t & 7;
    int n = n0 + row;
    if (n >= NN) return;
    float sum = 0.f;
    #pragma unroll
    for (int k = 0; k < DH; k++) sum += sx[row*68 + k] * sW[k*8 + c];
    if (c < 4) d_el[n*NH + c]     = sum;
    else       d_er[n*NH + c - 4] = sum;
}

// ---------------- fused gather-aggregate (warp per dst) ----------------------
// xm[d] += 0.25 * sum_h ( sum_e exp(leaky(el[s]+er[d])) * fs[s] ) / sum_e exp(...)
__global__ void aggregate(const int* __restrict__ off, const int* __restrict__ csrc) {
    int d = (blockIdx.x*blockDim.x + threadIdx.x) >> 5;
    int lane = threadIdx.x & 31;
    if (d >= NN) return;
    int j0 = off[d], j1 = off[d+1];
    if (j0 == j1) return;
    int h = lane >> 3;
    float erh = d_er[d*NH + h];
    float4 a = make_float4(0.f,0.f,0.f,0.f);
    float4 b = make_float4(0.f,0.f,0.f,0.f);
    float ssum = 0.f;
    for (int j = j0; j < j1; j++) {
        int s = csrc[j];                       // warp-broadcast load
        float e = d_el[s*NH + h] + erh;
        e = (e >= 0.f) ? e : 0.2f*e;
        e = __expf(e);
        ssum += e;
        const float4* fp = (const float4*)&d_fs[(size_t)s*FF + lane*8];
        float4 f0 = fp[0], f1 = fp[1];
        a.x += e*f0.x; a.y += e*f0.y; a.z += e*f0.z; a.w += e*f0.w;
        b.x += e*f1.x; b.y += e*f1.y; b.z += e*f1.z; b.w += e*f1.w;
    }
    float w = 0.25f * __frcp_rn(ssum);
    a.x *= w; a.y *= w; a.z *= w; a.w *= w;
    b.x *= w; b.y *= w; b.z *= w; b.w *= w;
    // reduce over heads: lanes l, l^8, l^16, l^24 hold same within-head cols
    #pragma unroll
    for (int m = 8; m <= 16; m <<= 1) {
        a.x += __shfl_xor_sync(0xffffffffu, a.x, m);
        a.y += __shfl_xor_sync(0xffffffffu, a.y, m);
        a.z += __shfl_xor_sync(0xffffffffu, a.z, m);
        a.w += __shfl_xor_sync(0xffffffffu, a.w, m);
        b.x += __shfl_xor_sync(0xffffffffu, b.x, m);
        b.y += __shfl_xor_sync(0xffffffffu, b.y, m);
        b.z += __shfl_xor_sync(0xffffffffu, b.z, m);
        b.w += __shfl_xor_sync(0xffffffffu, b.w, m);
    }
    if (lane < 8) {
        float* xp = &d_xm[(size_t)d*DH + lane*8];
        float4 o0 = ((float4*)xp)[0];
        float4 o1 = ((float4*)xp)[1];
        o0.x += a.x; o0.y += a.y; o0.z += a.z; o0.w += a.w;
        o1.x += b.x; o1.y += b.y; o1.z += b.z; o1.w += b.w;
        ((float4*)xp)[0] = o0;
        ((float4*)xp)[1] = o1;
    }
}

// ---------------- launch -----------------------------------------------------
extern "C" void kernel_launch(void* const* d_in, const int* in_sizes, int n_in,
                              void* d_out, int out_size) {
    const float* x0 = (const float*)d_in[0];
    const int* srcs[3] = {(const int*)d_in[1], (const int*)d_in[3], (const int*)d_in[5]};
    const int* dsts[3] = {(const int*)d_in[2], (const int*)d_in[4], (const int*)d_in[6]};
    int Es[3] = { in_sizes[1], in_sizes[3], in_sizes[5] };
    const float* Wl[2]   = {(const float*)d_in[7],  (const float*)d_in[12]};
    const float* all_[2] = {(const float*)d_in[8],  (const float*)d_in[13]};
    const float* arl[2]  = {(const float*)d_in[9],  (const float*)d_in[14]};
    const float* bl[2]   = {(const float*)d_in[10], (const float*)d_in[15]};
    const float* rWl[2]  = {(const float*)d_in[11], (const float*)d_in[16]};
    const float* fcWl[2] = {(const float*)d_in[17], (const float*)d_in[19]};
    const float* fcbl[2] = {(const float*)d_in[18], (const float*)d_in[20]};
    const float* gl[2]   = {(const float*)d_in[21], (const float*)d_in[23]};
    const float* bel[2]  = {(const float*)d_in[22], (const float*)d_in[24]};

    float *p_xb, *p_fs, *p_xm, *p_x1, *p_rWfold, *p_bfold, *p_Walr;
    int *p_off, *p_csrsrc;
    cudaGetSymbolAddress((void**)&p_xb,     d_xb);
    cudaGetSymbolAddress((void**)&p_fs,     d_fs);
    cudaGetSymbolAddress((void**)&p_xm,     d_xm);
    cudaGetSymbolAddress((void**)&p_x1,     d_x1);
    cudaGetSymbolAddress((void**)&p_rWfold, d_rWfold);
    cudaGetSymbolAddress((void**)&p_bfold,  d_bfold);
    cudaGetSymbolAddress((void**)&p_Walr,   d_Walr);
    cudaGetSymbolAddress((void**)&p_off,    d_off);
    cudaGetSymbolAddress((void**)&p_csrsrc, d_csrsrc);

    const int TPB = 256;
    dim3 gg((NN+63)/64, 4);     // fs GEMMs (Nn=256)
    dim3 gg64((NN+63)/64, 1);   // 64-col GEMMs

    // ---- CSR build (edge structure shared by both layers) ----
    for (int r = 0; r < 3; r++) {
        int E = Es[r];
        csr_zero<<<(NN+TPB-1)/TPB, TPB>>>();
        csr_hist<<<(E+TPB-1)/TPB, TPB>>>(dsts[r], E);
        csr_scan<<<1, 1024>>>(p_off + r*(NN+1));
        csr_fill<<<(E+TPB-1)/TPB, TPB>>>(srcs[r], dsts[r], p_csrsrc + r*EMAX, E);
    }

    for (int L = 0; L < 2; L++) {
        const float* xin = (L == 0) ? x0 : p_x1;
        float* xout = (L == 0) ? p_x1 : (float*)d_out;

        bn_stats_init<<<1, 64>>>();
        bn_reduce<<<256, 256>>>(xin);
        bn_apply<<<(NN*DH + TPB-1)/TPB, TPB>>>(xin, gl[L], bel[L]);

        prep_rwfold<<<(DH*DH + TPB-1)/TPB, TPB>>>(rWl[L], bl[L]);
        prep_walr<<<(3*DH*8 + TPB-1)/TPB, TPB>>>(Wl[L], all_[L], arl[L]);

        // residual (+bias, head-mean folded):  xm = xb @ rWfold + bfold
        gemm_k64<false,true><<<gg64, 256>>>(p_xb, p_rWfold, p_xm, p_bfold, NN, DH);

        for (int r = 0; r < 3; r++) {
            gemm_k64<false,false><<<gg, 256>>>(p_xb, Wl[L] + (size_t)r*DH*FF, p_fs,
                                               nullptr, NN, FF);
            elr_gemm<<<(NN+31)/32, 256>>>(p_Walr + r*DH*8);
            aggregate<<<(NN*32 + TPB-1)/TPB, TPB>>>(p_off + r*(NN+1), p_csrsrc + r*EMAX);
        }

        // fc + relu
        gemm_k64<true,true><<<gg64, 256>>>(p_xm, fcWl[L], xout, fcbl[L], NN, DH);
    }
}

// round 10
// speedup vs baseline: 4.1016x; 1.5775x over previous
#include <cuda_runtime.h>
#include <math.h>

#define NN 50000
#define DH 64
#define NH 4
#define FF 256      // NH*DH
#define F3 768      // 3*FF
#define EMAX 400000
#define TOT3 (3*NN)

// ---------------- scratch (device globals) -----------------------------------
static __device__ float d_xb[NN*DH];        // BN'd input
static __device__ float d_fs[(size_t)NN*F3];// projected features, all 3 relations
static __device__ float d_el[3*NN*NH];
static __device__ float d_er[3*NN*NH];
static __device__ float d_xm[NN*DH];        // residual + aggregated head-mean
static __device__ float d_x1[NN*DH];        // layer-1 output
static __device__ float d_rWfold[DH*DH];
static __device__ float d_bfold[DH];
static __device__ float d_Walr[3*DH*8];     // [r][k][8] (el cols 0-3, er 4-7)
static __device__ float d_colsum[DH];
static __device__ float d_colsq[DH];
// CSR (global over 3 relations)
static __device__ int d_cnt[TOT3];
static __device__ int d_cur[TOT3];
static __device__ int d_off[TOT3+1];
static __device__ int d_part[256];
static __device__ int d_csrsrc[3*EMAX];

// ---------------- f32x2 helpers ----------------------------------------------
__device__ __forceinline__ unsigned long long pack2(float x, float y) {
    unsigned long long r;
    asm("mov.b64 %0, {%1, %2};" : "=l"(r) : "f"(x), "f"(y));
    return r;
}
__device__ __forceinline__ void ffma2(unsigned long long& d, unsigned long long a,
                                      unsigned long long b) {
    asm("fma.rn.f32x2 %0, %1, %2, %0;" : "+l"(d) : "l"(a), "l"(b));
}
__device__ __forceinline__ float2 unpack2(unsigned long long v) {
    float2 f;
    asm("mov.b64 {%0, %1}, %2;" : "=f"(f.x), "=f"(f.y) : "l"(v));
    return f;
}

// ---------------- BN ---------------------------------------------------------
__global__ void bn_stats_init() {
    int t = threadIdx.x;
    if (t < DH) { d_colsum[t] = 0.f; d_colsq[t] = 0.f; }
}

__global__ void bn_reduce(const float* __restrict__ x) {
    int col = threadIdx.x & 63;
    int rg  = threadIdx.x >> 6;
    float s = 0.f, q = 0.f;
    for (int i = blockIdx.x*4 + rg; i < NN; i += gridDim.x*4) {
        float v = x[i*DH + col];
        s += v; q += v*v;
    }
    __shared__ float ss[256], sq[256];
    ss[threadIdx.x] = s; sq[threadIdx.x] = q;
    __syncthreads();
    if (threadIdx.x < 64) {
        s = ss[threadIdx.x] + ss[threadIdx.x+64] + ss[threadIdx.x+128] + ss[threadIdx.x+192];
        q = sq[threadIdx.x] + sq[threadIdx.x+64] + sq[threadIdx.x+128] + sq[threadIdx.x+192];
        atomicAdd(&d_colsum[threadIdx.x], s);
        atomicAdd(&d_colsq[threadIdx.x], q);
    }
}

__global__ void bn_apply(const float* __restrict__ x, const float* __restrict__ g,
                         const float* __restrict__ be) {
    int idx = blockIdx.x*blockDim.x + threadIdx.x;
    if (idx >= NN*DH) return;
    int c = idx & 63;
    float mu  = d_colsum[c] * (1.f/NN);
    float var = d_colsq[c] * (1.f/NN) - mu*mu;
    d_xb[idx] = (x[idx] - mu) * rsqrtf(var + 1e-5f) * g[c] + be[c];
}

// ---------------- parameter folding ------------------------------------------
__global__ void prep_rwfold(const float* __restrict__ rW, const float* __restrict__ b) {
    int idx = blockIdx.x*blockDim.x + threadIdx.x;
    if (idx < DH*DH) {
        int k = idx >> 6, c = idx & 63;
        float s = 0.f;
        #pragma unroll
        for (int r = 0; r < 3; r++)
            #pragma unroll
            for (int h = 0; h < NH; h++)
                s += rW[((size_t)r*DH + k)*FF + h*DH + c];
        d_rWfold[idx] = 0.25f * s;
    }
    if (idx < DH) {
        float s = 0.f;
        #pragma unroll
        for (int r = 0; r < 3; r++)
            #pragma unroll
            for (int h = 0; h < NH; h++)
                s += b[r*FF + h*DH + idx];
        d_bfold[idx] = 0.25f * s;
    }
}

__global__ void prep_walr(const float* __restrict__ W, const float* __restrict__ al,
                          const float* __restrict__ ar) {
    int idx = blockIdx.x*blockDim.x + threadIdx.x;
    if (idx >= 3*DH*8) return;
    int r = idx / (DH*8);
    int k = (idx >> 3) % DH;
    int c = idx & 7;
    int h = c & 3;
    const float* a = ((c < 4) ? al : ar) + ((size_t)r*NH + h)*DH;
    const float* w = W + ((size_t)r*DH + k)*FF + h*DH;
    float s = 0.f;
    #pragma unroll
    for (int d = 0; d < DH; d++) s += w[d]*a[d];
    d_Walr[idx] = s;
}

// ---------------- CSR build (global over 3 relations) -------------------------
__global__ void csr_zero() {
    int i = blockIdx.x*blockDim.x + threadIdx.x;
    if (i < TOT3) d_cnt[i] = 0;
}

__global__ void csr_hist(const int* __restrict__ dst, int E, int rbase) {
    int e = blockIdx.x*blockDim.x + threadIdx.x;
    if (e < E) atomicAdd(&d_cnt[rbase + dst[e]], 1);
}

__global__ void scan_blocks() {                 // grid 147, block 1024
    __shared__ int buf[1024];
    int t = threadIdx.x, g = blockIdx.x*1024 + t;
    int v = (g < TOT3) ? d_cnt[g] : 0;
    buf[t] = v;
    __syncthreads();
    #pragma unroll
    for (int s = 1; s < 1024; s <<= 1) {
        int x = (t >= s) ? buf[t-s] : 0;
        __syncthreads();
        buf[t] += x;
        __syncthreads();
    }
    if (g < TOT3) d_off[g] = buf[t] - v;        // local exclusive
    if (t == 1023) d_part[blockIdx.x] = buf[1023];
}

__global__ void scan_part(int nb) {             // 1 block, 256 threads
    __shared__ int buf[256];
    int t = threadIdx.x;
    int v = (t < nb) ? d_part[t] : 0;
    buf[t] = v;
    __syncthreads();
    #pragma unroll
    for (int s = 1; s < 256; s <<= 1) {
        int x = (t >= s) ? buf[t-s] : 0;
        __syncthreads();
        buf[t] += x;
        __syncthreads();
    }
    if (t < nb) d_part[t] = buf[t] - v;         // exclusive
}

__global__ void scan_add() {                    // grid 147, block 1024
    int g = blockIdx.x*1024 + threadIdx.x;
    if (g >= TOT3) return;
    int o = d_off[g] + d_part[blockIdx.x];
    d_off[g] = o;
    d_cur[g] = o;
    if (g == TOT3-1) d_off[TOT3] = o + d_cnt[g];
}

__global__ void csr_fill(const int* __restrict__ src, const int* __restrict__ dst,
                         int E, int rbase) {
    int e = blockIdx.x*blockDim.x + threadIdx.x;
    if (e >= E) return;
    int pos = atomicAdd(&d_cur[rbase + dst[e]], 1);
    d_csrsrc[pos] = src[e];
}

// ---------------- fs GEMM (all 3 relations): fs[m][r*256+n] = xb @ W[r] ------
__global__ void fs_gemm(const float* __restrict__ A, const float* __restrict__ W) {
    __shared__ float As[64][68];
    __shared__ float Bs[64][68];
    int r  = blockIdx.y >> 2;
    int n0 = (blockIdx.y & 3) * 64;
    int m0 = blockIdx.x * 64;
    const float* B = W + (size_t)r*DH*FF + n0;   // row stride FF
    int t = threadIdx.x;

    #pragma unroll
    for (int l = 0; l < 4; l++) {
        int lin = t + l*256;
        int row = lin >> 4, c4 = lin & 15;
        float4 v = make_float4(0.f,0.f,0.f,0.f);
        if (m0 + row < NN) v = *(const float4*)&A[(size_t)(m0+row)*64 + c4*4];
        *(float4*)&As[row][c4*4] = v;
        float4 w = *(const float4*)&B[(size_t)row*FF + c4*4];
        *(float4*)&Bs[row][c4*4] = w;
    }
    __syncthreads();

    int ty = t >> 4, tx = t & 15;
    unsigned long long acc[4][2] = {};
    #pragma unroll
    for (int k = 0; k < 64; k++) {
        unsigned long long b01 = *(const unsigned long long*)&Bs[k][tx*4];
        unsigned long long b23 = *(const unsigned long long*)&Bs[k][tx*4+2];
        #pragma unroll
        for (int i = 0; i < 4; i++) {
            float a = As[ty*4+i][k];
            unsigned long long aa = pack2(a, a);
            ffma2(acc[i][0], aa, b01);
            ffma2(acc[i][1], aa, b23);
        }
    }

    #pragma unroll
    for (int i = 0; i < 4; i++) {
        int m = m0 + ty*4 + i;
        if (m >= NN) continue;
        float2 lo = unpack2(acc[i][0]), hi = unpack2(acc[i][1]);
        float4 o = make_float4(lo.x, lo.y, hi.x, hi.y);
        *(float4*)&d_fs[(size_t)m*F3 + r*FF + n0 + tx*4] = o;
    }
}

// ---------------- GEMM Nn=64: C = A[M,64] @ B[64,64] (+bias)(+relu) ----------
template<bool RELU, bool BIAS>
__global__ void gemm64(const float* __restrict__ A, const float* __restrict__ B,
                       float* __restrict__ C, const float* __restrict__ bias) {
    __shared__ float As[64][68];
    __shared__ float Bs[64][68];
    int m0 = blockIdx.x * 64;
    int t = threadIdx.x;

    #pragma unroll
    for (int l = 0; l < 4; l++) {
        int lin = t + l*256;
        int row = lin >> 4, c4 = lin & 15;
        float4 v = make_float4(0.f,0.f,0.f,0.f);
        if (m0 + row < NN) v = *(const float4*)&A[(size_t)(m0+row)*64 + c4*4];
        *(float4*)&As[row][c4*4] = v;
        float4 w = *(const float4*)&B[(size_t)row*64 + c4*4];
        *(float4*)&Bs[row][c4*4] = w;
    }
    __syncthreads();

    int ty = t >> 4, tx = t & 15;
    unsigned long long acc[4][2] = {};
    #pragma unroll
    for (int k = 0; k < 64; k++) {
        unsigned long long b01 = *(const unsigned long long*)&Bs[k][tx*4];
        unsigned long long b23 = *(const unsigned long long*)&Bs[k][tx*4+2];
        #pragma unroll
        for (int i = 0; i < 4; i++) {
            float a = As[ty*4+i][k];
            unsigned long long aa = pack2(a, a);
            ffma2(acc[i][0], aa, b01);
            ffma2(acc[i][1], aa, b23);
        }
    }

    #pragma unroll
    for (int i = 0; i < 4; i++) {
        int m = m0 + ty*4 + i;
        if (m >= NN) continue;
        float2 lo = unpack2(acc[i][0]), hi = unpack2(acc[i][1]);
        float4 o = make_float4(lo.x, lo.y, hi.x, hi.y);
        if (BIAS) {
            o.x += bias[tx*4+0]; o.y += bias[tx*4+1];
            o.z += bias[tx*4+2]; o.w += bias[tx*4+3];
        }
        if (RELU) {
            o.x = fmaxf(o.x, 0.f); o.y = fmaxf(o.y, 0.f);
            o.z = fmaxf(o.z, 0.f); o.w = fmaxf(o.w, 0.f);
        }
        *(float4*)&C[(size_t)m*64 + tx*4] = o;
    }
}

// ---------------- el/er for all 3 relations: [el|er] = xb @ Walr -------------
__global__ void elr_gemm() {          // block 768 threads, 32 nodes per block
    __shared__ float sW[64*24];
    __shared__ float sx[32*68];
    int t = threadIdx.x;
    for (int i = t; i < 1536; i += 768) {         // remap [r][k][c] -> [k][r*8+c]
        int r = i >> 9, k = (i >> 3) & 63, c = i & 7;
        sW[k*24 + r*8 + c] = d_Walr[i];
    }
    int n0 = blockIdx.x * 32;
    for (int i = t; i < 512; i += 768) {
        int row = i >> 4, c4 = i & 15;
        float4 v = make_float4(0.f,0.f,0.f,0.f);
        if (n0 + row < NN) v = ((const float4*)&d_xb[(size_t)(n0+row)*64])[c4];
        *(float4*)&sx[row*68 + c4*4] = v;
    }
    __syncthreads();
    int row = t / 24, col = t - row*24;
    if (row >= 32) return;
    int n = n0 + row;
    if (n >= NN) return;
    float sum = 0.f;
    #pragma unroll
    for (int k = 0; k < 64; k++) sum += sx[row*68 + k] * sW[k*24 + col];
    int r = col >> 3, c = col & 7, h = c & 3;
    if (c < 4) d_el[((size_t)r*NN + n)*4 + h] = sum;
    else       d_er[((size_t)r*NN + n)*4 + h] = sum;
}

// ---------------- fused gather-aggregate (warp per dst, 4-edge unroll) -------
__device__ __forceinline__ float expleaky(float e) {
    e = (e >= 0.f) ? e : 0.2f*e;
    return __expf(e);
}

__global__ void aggregate(const int* __restrict__ off, const float* __restrict__ el,
                          const float* __restrict__ er, const float* __restrict__ fs) {
    int d = (blockIdx.x*blockDim.x + threadIdx.x) >> 5;
    int lane = threadIdx.x & 31;
    if (d >= NN) return;
    int j0 = off[d], j1 = off[d+1];
    if (j0 == j1) return;
    int h = lane >> 3;
    float erh = er[d*4 + h];
    float4 a = make_float4(0.f,0.f,0.f,0.f);
    float4 b = make_float4(0.f,0.f,0.f,0.f);
    float ssum = 0.f;
    int j = j0;
    for (; j + 4 <= j1; j += 4) {
        int s0 = d_csrsrc[j], s1 = d_csrsrc[j+1], s2 = d_csrsrc[j+2], s3 = d_csrsrc[j+3];
        float e0 = el[s0*4+h] + erh, e1 = el[s1*4+h] + erh;
        float e2 = el[s2*4+h] + erh, e3 = el[s3*4+h] + erh;
        const float4* f0 = (const float4*)&fs[(size_t)s0*F3 + lane*8];
        const float4* f1 = (const float4*)&fs[(size_t)s1*F3 + lane*8];
        const float4* f2 = (const float4*)&fs[(size_t)s2*F3 + lane*8];
        const float4* f3 = (const float4*)&fs[(size_t)s3*F3 + lane*8];
        float4 v00 = f0[0], v01 = f0[1];
        float4 v10 = f1[0], v11 = f1[1];
        float4 v20 = f2[0], v21 = f2[1];
        float4 v30 = f3[0], v31 = f3[1];
        e0 = expleaky(e0); e1 = expleaky(e1); e2 = expleaky(e2); e3 = expleaky(e3);
        ssum += (e0 + e1) + (e2 + e3);
        a.x += e0*v00.x + e1*v10.x + e2*v20.x + e3*v30.x;
        a.y += e0*v00.y + e1*v10.y + e2*v20.y + e3*v30.y;
        a.z += e0*v00.z + e1*v10.z + e2*v20.z + e3*v30.z;
        a.w += e0*v00.w + e1*v10.w + e2*v20.w + e3*v30.w;
        b.x += e0*v01.x + e1*v11.x + e2*v21.x + e3*v31.x;
        b.y += e0*v01.y + e1*v11.y + e2*v21.y + e3*v31.y;
        b.z += e0*v01.z + e1*v11.z + e2*v21.z + e3*v31.z;
        b.w += e0*v01.w + e1*v11.w + e2*v21.w + e3*v31.w;
    }
    for (; j < j1; j++) {
        int s = d_csrsrc[j];
        float e = expleaky(el[s*4+h] + erh);
        ssum += e;
        const float4* fp = (const float4*)&fs[(size_t)s*F3 + lane*8];
        float4 f0 = fp[0], f1 = fp[1];
        a.x += e*f0.x; a.y += e*f0.y; a.z += e*f0.z; a.w += e*f0.w;
        b.x += e*f1.x; b.y += e*f1.y; b.z += e*f1.z; b.w += e*f1.w;
    }
    float w = 0.25f * __frcp_rn(ssum);
    a.x *= w; a.y *= w; a.z *= w; a.w *= w;
    b.x *= w; b.y *= w; b.z *= w; b.w *= w;
    #pragma unroll
    for (int m = 8; m <= 16; m <<= 1) {
        a.x += __shfl_xor_sync(0xffffffffu, a.x, m);
        a.y += __shfl_xor_sync(0xffffffffu, a.y, m);
        a.z += __shfl_xor_sync(0xffffffffu, a.z, m);
        a.w += __shfl_xor_sync(0xffffffffu, a.w, m);
        b.x += __shfl_xor_sync(0xffffffffu, b.x, m);
        b.y += __shfl_xor_sync(0xffffffffu, b.y, m);
        b.z += __shfl_xor_sync(0xffffffffu, b.z, m);
        b.w += __shfl_xor_sync(0xffffffffu, b.w, m);
    }
    if (lane < 8) {
        float* xp = &d_xm[(size_t)d*DH + lane*8];
        float4 o0 = ((float4*)xp)[0];
        float4 o1 = ((float4*)xp)[1];
        o0.x += a.x; o0.y += a.y; o0.z += a.z; o0.w += a.w;
        o1.x += b.x; o1.y += b.y; o1.z += b.z; o1.w += b.w;
        ((float4*)xp)[0] = o0;
        ((float4*)xp)[1] = o1;
    }
}

// ---------------- launch -----------------------------------------------------
extern "C" void kernel_launch(void* const* d_in, const int* in_sizes, int n_in,
                              void* d_out, int out_size) {
    const float* x0 = (const float*)d_in[0];
    const int* srcs[3] = {(const int*)d_in[1], (const int*)d_in[3], (const int*)d_in[5]};
    const int* dsts[3] = {(const int*)d_in[2], (const int*)d_in[4], (const int*)d_in[6]};
    int Es[3] = { in_sizes[1], in_sizes[3], in_sizes[5] };
    const float* Wl[2]   = {(const float*)d_in[7],  (const float*)d_in[12]};
    const float* all_[2] = {(const float*)d_in[8],  (const float*)d_in[13]};
    const float* arl[2]  = {(const float*)d_in[9],  (const float*)d_in[14]};
    const float* bl[2]   = {(const float*)d_in[10], (const float*)d_in[15]};
    const float* rWl[2]  = {(const float*)d_in[11], (const float*)d_in[16]};
    const float* fcWl[2] = {(const float*)d_in[17], (const float*)d_in[19]};
    const float* fcbl[2] = {(const float*)d_in[18], (const float*)d_in[20]};
    const float* gl[2]   = {(const float*)d_in[21], (const float*)d_in[23]};
    const float* bel[2]  = {(const float*)d_in[22], (const float*)d_in[24]};

    float *p_xb, *p_fs, *p_xm, *p_x1, *p_rWfold, *p_bfold, *p_el, *p_er;
    int *p_off;
    cudaGetSymbolAddress((void**)&p_xb,     d_xb);
    cudaGetSymbolAddress((void**)&p_fs,     d_fs);
    cudaGetSymbolAddress((void**)&p_xm,     d_xm);
    cudaGetSymbolAddress((void**)&p_x1,     d_x1);
    cudaGetSymbolAddress((void**)&p_rWfold, d_rWfold);
    cudaGetSymbolAddress((void**)&p_bfold,  d_bfold);
    cudaGetSymbolAddress((void**)&p_el,     d_el);
    cudaGetSymbolAddress((void**)&p_er,     d_er);
    cudaGetSymbolAddress((void**)&p_off,    d_off);

    const int TPB = 256;
    const int NB_SCAN = (TOT3 + 1023) / 1024;   // 147

    // ---- CSR build (shared by both layers) ----
    csr_zero<<<(TOT3+TPB-1)/TPB, TPB>>>();
    for (int r = 0; r < 3; r++)
        csr_hist<<<(Es[r]+TPB-1)/TPB, TPB>>>(dsts[r], Es[r], r*NN);
    scan_blocks<<<NB_SCAN, 1024>>>();
    scan_part<<<1, 256>>>(NB_SCAN);
    scan_add<<<NB_SCAN, 1024>>>();
    for (int r = 0; r < 3; r++)
        csr_fill<<<(Es[r]+TPB-1)/TPB, TPB>>>(srcs[r], dsts[r], Es[r], r*NN);

    dim3 gfs((NN+63)/64, 12);
    for (int L = 0; L < 2; L++) {
        const float* xin = (L == 0) ? x0 : p_x1;
        float* xout = (L == 0) ? p_x1 : (float*)d_out;

        bn_stats_init<<<1, 64>>>();
        bn_reduce<<<256, 256>>>(xin);
        bn_apply<<<(NN*DH + TPB-1)/TPB, TPB>>>(xin, gl[L], bel[L]);

        prep_rwfold<<<(DH*DH + TPB-1)/TPB, TPB>>>(rWl[L], bl[L]);
        prep_walr<<<(3*DH*8 + TPB-1)/TPB, TPB>>>(Wl[L], all_[L], arl[L]);

        // residual (+bias, head-mean folded): xm = xb @ rWfold + bfold
        gemm64<false,true><<<(NN+63)/64, 256>>>(p_xb, p_rWfold, p_xm, p_bfold);

        fs_gemm<<<gfs, 256>>>(p_xb, Wl[L]);
        elr_gemm<<<(NN+31)/32, 768>>>();

        for (int r = 0; r < 3; r++)
            aggregate<<<(NN*32 + TPB-1)/TPB, TPB>>>(p_off + r*NN,
                                                    p_el + (size_t)r*NN*4,
                                                    p_er + (size_t)r*NN*4,
                                                    p_fs + r*FF);

        // fc + relu
        gemm64<true,true><<<(NN+63)/64, 256>>>(p_xm, fcWl[L], xout, fcbl[L]);
    }
}

// round 15
// speedup vs baseline: 4.6465x; 1.1328x over previous
#include <cuda_runtime.h>
#include <cuda_fp16.h>
#include <math.h>

#define NN 50000
#define DH 64
#define NH 4
#define FF 256      // NH*DH
#define EMAX 400000
#define TOT3 (3*NN)

// ---------------- scratch (device globals) -----------------------------------
static __device__ float d_xb[NN*DH];        // BN'd input
static __device__ __half d_fsh[(size_t)3*NN*FF]; // projected feats, [r][N][256] fp16
static __device__ float d_el[3*NN*NH];
static __device__ float d_er[3*NN*NH];
static __device__ float d_xm[NN*DH];        // residual + aggregated head-mean
static __device__ float d_x1[NN*DH];        // layer-1 output
static __device__ float d_rWfold[DH*DH];
static __device__ float d_bfold[DH];
static __device__ float d_Walr[3*DH*8];     // [r][k][8] (el cols 0-3, er 4-7)
static __device__ float d_colsum[DH];
static __device__ float d_colsq[DH];
// CSR (global over 3 relations)
static __device__ int d_cnt[TOT3];
static __device__ int d_cur[TOT3];
static __device__ int d_off[TOT3+1];
static __device__ int d_part[256];
static __device__ int d_csrsrc[3*EMAX];

// ---------------- f32x2 / fp16 helpers ---------------------------------------
__device__ __forceinline__ unsigned long long pack2(float x, float y) {
    unsigned long long r;
    asm("mov.b64 %0, {%1, %2};" : "=l"(r) : "f"(x), "f"(y));
    return r;
}
__device__ __forceinline__ void ffma2(unsigned long long& d, unsigned long long a,
                                      unsigned long long b) {
    asm("fma.rn.f32x2 %0, %1, %2, %0;" : "+l"(d) : "l"(a), "l"(b));
}
__device__ __forceinline__ float2 unpack2(unsigned long long v) {
    float2 f;
    asm("mov.b64 {%0, %1}, %2;" : "=f"(f.x), "=f"(f.y) : "l"(v));
    return f;
}
__device__ __forceinline__ unsigned hpack(float x, float y) {
    __half2 h = __floats2half2_rn(x, y);
    return *(unsigned*)&h;
}
__device__ __forceinline__ float2 hunpack(unsigned u) {
    __half2 h = *(__half2*)&u;
    return __half22float2(h);
}

// ---------------- BN ---------------------------------------------------------
__global__ void bn_stats_init() {
    int t = threadIdx.x;
    if (t < DH) { d_colsum[t] = 0.f; d_colsq[t] = 0.f; }
}

__global__ void bn_reduce(const float* __restrict__ x) {
    int col = threadIdx.x & 63;
    int rg  = threadIdx.x >> 6;
    float s = 0.f, q = 0.f;
    for (int i = blockIdx.x*4 + rg; i < NN; i += gridDim.x*4) {
        float v = x[i*DH + col];
        s += v; q += v*v;
    }
    __shared__ float ss[256], sq[256];
    ss[threadIdx.x] = s; sq[threadIdx.x] = q;
    __syncthreads();
    if (threadIdx.x < 64) {
        s = ss[threadIdx.x] + ss[threadIdx.x+64] + ss[threadIdx.x+128] + ss[threadIdx.x+192];
        q = sq[threadIdx.x] + sq[threadIdx.x+64] + sq[threadIdx.x+128] + sq[threadIdx.x+192];
        atomicAdd(&d_colsum[threadIdx.x], s);
        atomicAdd(&d_colsq[threadIdx.x], q);
    }
}

__global__ void bn_apply(const float* __restrict__ x, const float* __restrict__ g,
                         const float* __restrict__ be) {
    int idx = blockIdx.x*blockDim.x + threadIdx.x;
    if (idx >= NN*DH) return;
    int c = idx & 63;
    float mu  = d_colsum[c] * (1.f/NN);
    float var = d_colsq[c] * (1.f/NN) - mu*mu;
    d_xb[idx] = (x[idx] - mu) * rsqrtf(var + 1e-5f) * g[c] + be[c];
}

// ---------------- parameter folding ------------------------------------------
__global__ void prep_rwfold(const float* __restrict__ rW, const float* __restrict__ b) {
    int idx = blockIdx.x*blockDim.x + threadIdx.x;
    if (idx < DH*DH) {
        int k = idx >> 6, c = idx & 63;
        float s = 0.f;
        #pragma unroll
        for (int r = 0; r < 3; r++)
            #pragma unroll
            for (int h = 0; h < NH; h++)
                s += rW[((size_t)r*DH + k)*FF + h*DH + c];
        d_rWfold[idx] = 0.25f * s;
    }
    if (idx < DH) {
        float s = 0.f;
        #pragma unroll
        for (int r = 0; r < 3; r++)
            #pragma unroll
            for (int h = 0; h < NH; h++)
                s += b[r*FF + h*DH + idx];
        d_bfold[idx] = 0.25f * s;
    }
}

__global__ void prep_walr(const float* __restrict__ W, const float* __restrict__ al,
                          const float* __restrict__ ar) {
    int idx = blockIdx.x*blockDim.x + threadIdx.x;
    if (idx >= 3*DH*8) return;
    int r = idx / (DH*8);
    int k = (idx >> 3) % DH;
    int c = idx & 7;
    int h = c & 3;
    const float* a = ((c < 4) ? al : ar) + ((size_t)r*NH + h)*DH;
    const float* w = W + ((size_t)r*DH + k)*FF + h*DH;
    float s = 0.f;
    #pragma unroll
    for (int d = 0; d < DH; d++) s += w[d]*a[d];
    d_Walr[idx] = s;
}

// ---------------- CSR build (global over 3 relations) -------------------------
__global__ void csr_zero() {
    int i = blockIdx.x*blockDim.x + threadIdx.x;
    if (i < TOT3) d_cnt[i] = 0;
}

__global__ void csr_hist(const int* __restrict__ dst, int E, int rbase) {
    int e = blockIdx.x*blockDim.x + threadIdx.x;
    if (e < E) atomicAdd(&d_cnt[rbase + dst[e]], 1);
}

__global__ void scan_blocks() {                 // grid 147, block 1024
    __shared__ int buf[1024];
    int t = threadIdx.x, g = blockIdx.x*1024 + t;
    int v = (g < TOT3) ? d_cnt[g] : 0;
    buf[t] = v;
    __syncthreads();
    #pragma unroll
    for (int s = 1; s < 1024; s <<= 1) {
        int x = (t >= s) ? buf[t-s] : 0;
        __syncthreads();
        buf[t] += x;
        __syncthreads();
    }
    if (g < TOT3) d_off[g] = buf[t] - v;        // local exclusive
    if (t == 1023) d_part[blockIdx.x] = buf[1023];
}

__global__ void scan_part(int nb) {             // 1 block, 256 threads
    __shared__ int buf[256];
    int t = threadIdx.x;
    int v = (t < nb) ? d_part[t] : 0;
    buf[t] = v;
    __syncthreads();
    #pragma unroll
    for (int s = 1; s < 256; s <<= 1) {
        int x = (t >= s) ? buf[t-s] : 0;
        __syncthreads();
        buf[t] += x;
        __syncthreads();
    }
    if (t < nb) d_part[t] = buf[t] - v;         // exclusive
}

__global__ void scan_add() {                    // grid 147, block 1024
    int g = blockIdx.x*1024 + threadIdx.x;
    if (g >= TOT3) return;
    int o = d_off[g] + d_part[blockIdx.x];
    d_off[g] = o;
    d_cur[g] = o;
    if (g == TOT3-1) d_off[TOT3] = o + d_cnt[g];
}

__global__ void csr_fill(const int* __restrict__ src, const int* __restrict__ dst,
                         int E, int rbase) {
    int e = blockIdx.x*blockDim.x + threadIdx.x;
    if (e >= E) return;
    int pos = atomicAdd(&d_cur[rbase + dst[e]], 1);
    d_csrsrc[pos] = src[e];
}

// ---------------- fs GEMM (one relation): fsh[r][m][n] = xb @ W[r], fp16 out --
__global__ void fs_gemm(const float* __restrict__ A, const float* __restrict__ W,
                        int r) {
    __shared__ float As[64][68];
    __shared__ float Bs[64][68];
    int n0 = blockIdx.y * 64;
    int m0 = blockIdx.x * 64;
    const float* B = W + (size_t)r*DH*FF + n0;   // row stride FF
    int t = threadIdx.x;

    #pragma unroll
    for (int l = 0; l < 4; l++) {
        int lin = t + l*256;
        int row = lin >> 4, c4 = lin & 15;
        float4 v = make_float4(0.f,0.f,0.f,0.f);
        if (m0 + row < NN) v = *(const float4*)&A[(size_t)(m0+row)*64 + c4*4];
        *(float4*)&As[row][c4*4] = v;
        float4 w = *(const float4*)&B[(size_t)row*FF + c4*4];
        *(float4*)&Bs[row][c4*4] = w;
    }
    __syncthreads();

    int ty = t >> 4, tx = t & 15;
    unsigned long long acc[4][2] = {};
    #pragma unroll
    for (int k = 0; k < 64; k++) {
        unsigned long long b01 = *(const unsigned long long*)&Bs[k][tx*4];
        unsigned long long b23 = *(const unsigned long long*)&Bs[k][tx*4+2];
        #pragma unroll
        for (int i = 0; i < 4; i++) {
            float a = As[ty*4+i][k];
            unsigned long long aa = pack2(a, a);
            ffma2(acc[i][0], aa, b01);
            ffma2(acc[i][1], aa, b23);
        }
    }

    #pragma unroll
    for (int i = 0; i < 4; i++) {
        int m = m0 + ty*4 + i;
        if (m >= NN) continue;
        float2 lo = unpack2(acc[i][0]), hi = unpack2(acc[i][1]);
        uint2 u = make_uint2(hpack(lo.x, lo.y), hpack(hi.x, hi.y));
        *(uint2*)&d_fsh[((size_t)r*NN + m)*FF + n0 + tx*4] = u;
    }
}

// ---------------- GEMM Nn=64: C = A[M,64] @ B[64,64] (+bias)(+relu) ----------
template<bool RELU, bool BIAS>
__global__ void gemm64(const float* __restrict__ A, const float* __restrict__ B,
                       float* __restrict__ C, const float* __restrict__ bias) {
    __shared__ float As[64][68];
    __shared__ float Bs[64][68];
    int m0 = blockIdx.x * 64;
    int t = threadIdx.x;

    #pragma unroll
    for (int l = 0; l < 4; l++) {
        int lin = t + l*256;
        int row = lin >> 4, c4 = lin & 15;
        float4 v = make_float4(0.f,0.f,0.f,0.f);
        if (m0 + row < NN) v = *(const float4*)&A[(size_t)(m0+row)*64 + c4*4];
        *(float4*)&As[row][c4*4] = v;
        float4 w = *(const float4*)&B[(size_t)row*64 + c4*4];
        *(float4*)&Bs[row][c4*4] = w;
    }
    __syncthreads();

    int ty = t >> 4, tx = t & 15;
    unsigned long long acc[4][2] = {};
    #pragma unroll
    for (int k = 0; k < 64; k++) {
        unsigned long long b01 = *(const unsigned long long*)&Bs[k][tx*4];
        unsigned long long b23 = *(const unsigned long long*)&Bs[k][tx*4+2];
        #pragma unroll
        for (int i = 0; i < 4; i++) {
            float a = As[ty*4+i][k];
            unsigned long long aa = pack2(a, a);
            ffma2(acc[i][0], aa, b01);
            ffma2(acc[i][1], aa, b23);
        }
    }

    #pragma unroll
    for (int i = 0; i < 4; i++) {
        int m = m0 + ty*4 + i;
        if (m >= NN) continue;
        float2 lo = unpack2(acc[i][0]), hi = unpack2(acc[i][1]);
        float4 o = make_float4(lo.x, lo.y, hi.x, hi.y);
        if (BIAS) {
            o.x += bias[tx*4+0]; o.y += bias[tx*4+1];
            o.z += bias[tx*4+2]; o.w += bias[tx*4+3];
        }
        if (RELU) {
            o.x = fmaxf(o.x, 0.f); o.y = fmaxf(o.y, 0.f);
            o.z = fmaxf(o.z, 0.f); o.w = fmaxf(o.w, 0.f);
        }
        *(float4*)&C[(size_t)m*64 + tx*4] = o;
    }
}

// ---------------- el/er for all 3 relations: [el|er] = xb @ Walr -------------
__global__ void elr_gemm() {          // block 768 threads, 32 nodes per block
    __shared__ float sW[64*24];
    __shared__ float sx[32*68];
    int t = threadIdx.x;
    for (int i = t; i < 1536; i += 768) {         // remap [r][k][c] -> [k][r*8+c]
        int r = i >> 9, k = (i >> 3) & 63, c = i & 7;
        sW[k*24 + r*8 + c] = d_Walr[i];
    }
    int n0 = blockIdx.x * 32;
    for (int i = t; i < 512; i += 768) {
        int row = i >> 4, c4 = i & 15;
        float4 v = make_float4(0.f,0.f,0.f,0.f);
        if (n0 + row < NN) v = ((const float4*)&d_xb[(size_t)(n0+row)*64])[c4];
        *(float4*)&sx[row*68 + c4*4] = v;
    }
    __syncthreads();
    int row = t / 24, col = t - row*24;
    if (row >= 32) return;
    int n = n0 + row;
    if (n >= NN) return;
    float sum = 0.f;
    #pragma unroll
    for (int k = 0; k < 64; k++) sum += sx[row*68 + k] * sW[k*24 + col];
    int r = col >> 3, c = col & 7, h = c & 3;
    if (c < 4) d_el[((size_t)r*NN + n)*4 + h] = sum;
    else       d_er[((size_t)r*NN + n)*4 + h] = sum;
}

// ---------------- fused gather-aggregate (warp per dst, fp16 fs) --------------
__device__ __forceinline__ float expleaky(float e) {
    e = (e >= 0.f) ? e : 0.2f*e;
    return __expf(e);
}

__global__ void aggregate(const int* __restrict__ off, const float* __restrict__ el,
                          const float* __restrict__ er,
                          const __half* __restrict__ fsh) {
    int d = (blockIdx.x*blockDim.x + threadIdx.x) >> 5;
    int lane = threadIdx.x & 31;
    if (d >= NN) return;
    int j0 = off[d], j1 = off[d+1];
    if (j0 == j1) return;
    int h = lane >> 3;
    float erh = er[d*4 + h];
    float4 a = make_float4(0.f,0.f,0.f,0.f);
    float4 b = make_float4(0.f,0.f,0.f,0.f);
    float ssum = 0.f;
    int j = j0;
    for (; j + 4 <= j1; j += 4) {
        int s0 = d_csrsrc[j], s1 = d_csrsrc[j+1], s2 = d_csrsrc[j+2], s3 = d_csrsrc[j+3];
        float e0 = el[s0*4+h] + erh, e1 = el[s1*4+h] + erh;
        float e2 = el[s2*4+h] + erh, e3 = el[s3*4+h] + erh;
        uint4 v0 = *(const uint4*)&fsh[(size_t)s0*FF + lane*8];
        uint4 v1 = *(const uint4*)&fsh[(size_t)s1*FF + lane*8];
        uint4 v2 = *(const uint4*)&fsh[(size_t)s2*FF + lane*8];
        uint4 v3 = *(const uint4*)&fsh[(size_t)s3*FF + lane*8];
        e0 = expleaky(e0); e1 = expleaky(e1); e2 = expleaky(e2); e3 = expleaky(e3);
        ssum += (e0 + e1) + (e2 + e3);
        {
            float2 p0 = hunpack(v0.x), p1 = hunpack(v1.x), p2 = hunpack(v2.x), p3 = hunpack(v3.x);
            a.x += e0*p0.x + e1*p1.x + e2*p2.x + e3*p3.x;
            a.y += e0*p0.y + e1*p1.y + e2*p2.y + e3*p3.y;
        }
        {
            float2 p0 = hunpack(v0.y), p1 = hunpack(v1.y), p2 = hunpack(v2.y), p3 = hunpack(v3.y);
            a.z += e0*p0.x + e1*p1.x + e2*p2.x + e3*p3.x;
            a.w += e0*p0.y + e1*p1.y + e2*p2.y + e3*p3.y;
        }
        {
            float2 p0 = hunpack(v0.z), p1 = hunpack(v1.z), p2 = hunpack(v2.z), p3 = hunpack(v3.z);
            b.x += e0*p0.x + e1*p1.x + e2*p2.x + e3*p3.x;
            b.y += e0*p0.y + e1*p1.y + e2*p2.y + e3*p3.y;
        }
        {
            float2 p0 = hunpack(v0.w), p1 = hunpack(v1.w), p2 = hunpack(v2.w), p3 = hunpack(v3.w);
            b.z += e0*p0.x + e1*p1.x + e2*p2.x + e3*p3.x;
            b.w += e0*p0.y + e1*p1.y + e2*p2.y + e3*p3.y;
        }
    }
    for (; j < j1; j++) {
        int s = d_csrsrc[j];
        float e = expleaky(el[s*4+h] + erh);
        ssum += e;
        uint4 v = *(const uint4*)&fsh[(size_t)s*FF + lane*8];
        float2 p0 = hunpack(v.x), p1 = hunpack(v.y), p2 = hunpack(v.z), p3 = hunpack(v.w);
        a.x += e*p0.x; a.y += e*p0.y;
        a.z += e*p1.x; a.w += e*p1.y;
        b.x += e*p2.x; b.y += e*p2.y;
        b.z += e*p3.x; b.w += e*p3.y;
    }
    float w = 0.25f * __frcp_rn(ssum);
    a.x *= w; a.y *= w; a.z *= w; a.w *= w;
    b.x *= w; b.y *= w; b.z *= w; b.w *= w;
    #pragma unroll
    for (int m = 8; m <= 16; m <<= 1) {
        a.x += __shfl_xor_sync(0xffffffffu, a.x, m);
        a.y += __shfl_xor_sync(0xffffffffu, a.y, m);
        a.z += __shfl_xor_sync(0xffffffffu, a.z, m);
        a.w += __shfl_xor_sync(0xffffffffu, a.w, m);
        b.x += __shfl_xor_sync(0xffffffffu, b.x, m);
        b.y += __shfl_xor_sync(0xffffffffu, b.y, m);
        b.z += __shfl_xor_sync(0xffffffffu, b.z, m);
        b.w += __shfl_xor_sync(0xffffffffu, b.w, m);
    }
    if (lane < 8) {
        float* xp = &d_xm[(size_t)d*DH + lane*8];
        float4 o0 = ((float4*)xp)[0];
        float4 o1 = ((float4*)xp)[1];
        o0.x += a.x; o0.y += a.y; o0.z += a.z; o0.w += a.w;
        o1.x += b.x; o1.y += b.y; o1.z += b.z; o1.w += b.w;
        ((float4*)xp)[0] = o0;
        ((float4*)xp)[1] = o1;
    }
}

// ---------------- launch -----------------------------------------------------
extern "C" void kernel_launch(void* const* d_in, const int* in_sizes, int n_in,
                              void* d_out, int out_size) {
    const float* x0 = (const float*)d_in[0];
    const int* srcs[3] = {(const int*)d_in[1], (const int*)d_in[3], (const int*)d_in[5]};
    const int* dsts[3] = {(const int*)d_in[2], (const int*)d_in[4], (const int*)d_in[6]};
    int Es[3] = { in_sizes[1], in_sizes[3], in_sizes[5] };
    const float* Wl[2]   = {(const float*)d_in[7],  (const float*)d_in[12]};
    const float* all_[2] = {(const float*)d_in[8],  (const float*)d_in[13]};
    const float* arl[2]  = {(const float*)d_in[9],  (const float*)d_in[14]};
    const float* bl[2]   = {(const float*)d_in[10], (const float*)d_in[15]};
    const float* rWl[2]  = {(const float*)d_in[11], (const float*)d_in[16]};
    const float* fcWl[2] = {(const float*)d_in[17], (const float*)d_in[19]};
    const float* fcbl[2] = {(const float*)d_in[18], (const float*)d_in[20]};
    const float* gl[2]   = {(const float*)d_in[21], (const float*)d_in[23]};
    const float* bel[2]  = {(const float*)d_in[22], (const float*)d_in[24]};

    float *p_xb, *p_xm, *p_x1, *p_rWfold, *p_bfold, *p_el, *p_er;
    __half *p_fsh;
    int *p_off;
    cudaGetSymbolAddress((void**)&p_xb,     d_xb);
    cudaGetSymbolAddress((void**)&p_fsh,    d_fsh);
    cudaGetSymbolAddress((void**)&p_xm,     d_xm);
    cudaGetSymbolAddress((void**)&p_x1,     d_x1);
    cudaGetSymbolAddress((void**)&p_rWfold, d_rWfold);
    cudaGetSymbolAddress((void**)&p_bfold,  d_bfold);
    cudaGetSymbolAddress((void**)&p_el,     d_el);
    cudaGetSymbolAddress((void**)&p_er,     d_er);
    cudaGetSymbolAddress((void**)&p_off,    d_off);

    const int TPB = 256;
    const int NB_SCAN = (TOT3 + 1023) / 1024;   // 147

    // ---- CSR build (shared by both layers) ----
    csr_zero<<<(TOT3+TPB-1)/TPB, TPB>>>();
    for (int r = 0; r < 3; r++)
        csr_hist<<<(Es[r]+TPB-1)/TPB, TPB>>>(dsts[r], Es[r], r*NN);
    scan_blocks<<<NB_SCAN, 1024>>>();
    scan_part<<<1, 256>>>(NB_SCAN);
    scan_add<<<NB_SCAN, 1024>>>();
    for (int r = 0; r < 3; r++)
        csr_fill<<<(Es[r]+TPB-1)/TPB, TPB>>>(srcs[r], dsts[r], Es[r], r*NN);

    dim3 gfs((NN+63)/64, 4);
    for (int L = 0; L < 2; L++) {
        const float* xin = (L == 0) ? x0 : p_x1;
        float* xout = (L == 0) ? p_x1 : (float*)d_out;

        bn_stats_init<<<1, 64>>>();
        bn_reduce<<<256, 256>>>(xin);
        bn_apply<<<(NN*DH + TPB-1)/TPB, TPB>>>(xin, gl[L], bel[L]);

        prep_rwfold<<<(DH*DH + TPB-1)/TPB, TPB>>>(rWl[L], bl[L]);
        prep_walr<<<(3*DH*8 + TPB-1)/TPB, TPB>>>(Wl[L], all_[L], arl[L]);

        // residual (+bias, head-mean folded): xm = xb @ rWfold + bfold
        gemm64<false,true><<<(NN+63)/64, 256>>>(p_xb, p_rWfold, p_xm, p_bfold);

        elr_gemm<<<(NN+31)/32, 768>>>();

        // per-relation producer->consumer so the 25.6MB fp16 fs slice stays in L2
        for (int r = 0; r < 3; r++) {
            fs_gemm<<<gfs, 256>>>(p_xb, Wl[L], r);
            aggregate<<<(NN*32 + TPB-1)/TPB, TPB>>>(p_off + r*NN,
                                                    p_el + (size_t)r*NN*4,
                                                    p_er + (size_t)r*NN*4,
                                                    p_fsh + (size_t)r*NN*FF);
        }

        // fc + relu
        gemm64<true,true><<<(NN+63)/64, 256>>>(p_xm, fcWl[L], xout, fcbl[L]);
    }
}

// round 16
// speedup vs baseline: 5.0265x; 1.0818x over previous
#include <cuda_runtime.h>
#include <cuda_fp16.h>
#include <math.h>

#define NN 50000
#define DH 64
#define NH 4
#define FF 256      // NH*DH
#define EMAX 400000
#define TOT3 (3*NN)

// ---------------- scratch (device globals) -----------------------------------
static __device__ float d_xb[NN*DH];        // BN'd input (fp32)
static __device__ __half d_xh[NN*DH];       // BN'd input (fp16, HMMA A operand)
static __device__ __half d_fsh[(size_t)3*NN*FF]; // projected feats [r][N][256] fp16
static __device__ __half d_Whp[3*FF*DH];    // W col-major fp16: [r][n][k]
static __device__ float d_el[3*NN*NH];
static __device__ float d_er[3*NN*NH];
static __device__ float d_xm[NN*DH];        // residual + aggregated head-mean
static __device__ float d_x1[NN*DH];        // layer-1 output
static __device__ float d_rWfold[DH*DH];
static __device__ float d_bfold[DH];
static __device__ float d_Walr[3*DH*8];     // [r][k][8] (el cols 0-3, er 4-7)
static __device__ float d_colsum[DH];
static __device__ float d_colsq[DH];
// CSR (global over 3 relations)
static __device__ int d_cnt[TOT3];
static __device__ int d_cur[TOT3];
static __device__ int d_off[TOT3+1];
static __device__ int d_part[256];
static __device__ int d_csrsrc[3*EMAX];

// ---------------- f32x2 / fp16 helpers ---------------------------------------
__device__ __forceinline__ unsigned long long pack2(float x, float y) {
    unsigned long long r;
    asm("mov.b64 %0, {%1, %2};" : "=l"(r) : "f"(x), "f"(y));
    return r;
}
__device__ __forceinline__ void ffma2(unsigned long long& d, unsigned long long a,
                                      unsigned long long b) {
    asm("fma.rn.f32x2 %0, %1, %2, %0;" : "+l"(d) : "l"(a), "l"(b));
}
__device__ __forceinline__ float2 unpack2(unsigned long long v) {
    float2 f;
    asm("mov.b64 {%0, %1}, %2;" : "=f"(f.x), "=f"(f.y) : "l"(v));
    return f;
}
__device__ __forceinline__ unsigned hpack(float x, float y) {
    __half2 h = __floats2half2_rn(x, y);
    return *(unsigned*)&h;
}
__device__ __forceinline__ float2 hunpack(unsigned u) {
    __half2 h = *(__half2*)&u;
    return __half22float2(h);
}

// ---------------- BN ---------------------------------------------------------
__global__ void bn_stats_init() {
    int t = threadIdx.x;
    if (t < DH) { d_colsum[t] = 0.f; d_colsq[t] = 0.f; }
}

__global__ void bn_reduce(const float* __restrict__ x) {
    int col = threadIdx.x & 63;
    int rg  = threadIdx.x >> 6;
    float s = 0.f, q = 0.f;
    for (int i = blockIdx.x*4 + rg; i < NN; i += gridDim.x*4) {
        float v = x[i*DH + col];
        s += v; q += v*v;
    }
    __shared__ float ss[256], sq[256];
    ss[threadIdx.x] = s; sq[threadIdx.x] = q;
    __syncthreads();
    if (threadIdx.x < 64) {
        s = ss[threadIdx.x] + ss[threadIdx.x+64] + ss[threadIdx.x+128] + ss[threadIdx.x+192];
        q = sq[threadIdx.x] + sq[threadIdx.x+64] + sq[threadIdx.x+128] + sq[threadIdx.x+192];
        atomicAdd(&d_colsum[threadIdx.x], s);
        atomicAdd(&d_colsq[threadIdx.x], q);
    }
}

__global__ void bn_apply(const float* __restrict__ x, const float* __restrict__ g,
                         const float* __restrict__ be) {
    int idx = blockIdx.x*blockDim.x + threadIdx.x;
    if (idx >= NN*DH) return;
    int c = idx & 63;
    float mu  = d_colsum[c] * (1.f/NN);
    float var = d_colsq[c] * (1.f/NN) - mu*mu;
    float v = (x[idx] - mu) * rsqrtf(var + 1e-5f) * g[c] + be[c];
    d_xb[idx] = v;
    d_xh[idx] = __float2half(v);
}

// ---------------- parameter folding ------------------------------------------
__global__ void prep_rwfold(const float* __restrict__ rW, const float* __restrict__ b) {
    int idx = blockIdx.x*blockDim.x + threadIdx.x;
    if (idx < DH*DH) {
        int k = idx >> 6, c = idx & 63;
        float s = 0.f;
        #pragma unroll
        for (int r = 0; r < 3; r++)
            #pragma unroll
            for (int h = 0; h < NH; h++)
                s += rW[((size_t)r*DH + k)*FF + h*DH + c];
        d_rWfold[idx] = 0.25f * s;
    }
    if (idx < DH) {
        float s = 0.f;
        #pragma unroll
        for (int r = 0; r < 3; r++)
            #pragma unroll
            for (int h = 0; h < NH; h++)
                s += b[r*FF + h*DH + idx];
        d_bfold[idx] = 0.25f * s;
    }
}

__global__ void prep_walr(const float* __restrict__ W, const float* __restrict__ al,
                          const float* __restrict__ ar) {
    int idx = blockIdx.x*blockDim.x + threadIdx.x;
    if (idx >= 3*DH*8) return;
    int r = idx / (DH*8);
    int k = (idx >> 3) % DH;
    int c = idx & 7;
    int h = c & 3;
    const float* a = ((c < 4) ? al : ar) + ((size_t)r*NH + h)*DH;
    const float* w = W + ((size_t)r*DH + k)*FF + h*DH;
    float s = 0.f;
    #pragma unroll
    for (int d = 0; d < DH; d++) s += w[d]*a[d];
    d_Walr[idx] = s;
}

// Whp[r][n][k] = fp16( W[r][k][n] )  (col-major for HMMA B operand)
__global__ void wh_prep(const float* __restrict__ W) {
    int idx = blockIdx.x*blockDim.x + threadIdx.x;
    if (idx >= 3*FF*DH) return;
    int r = idx / (FF*DH);
    int n = (idx / DH) % FF;
    int k = idx % DH;
    d_Whp[idx] = __float2half(W[((size_t)r*DH + k)*FF + n]);
}

// ---------------- CSR build (global over 3 relations) -------------------------
__global__ void csr_zero() {
    int i = blockIdx.x*blockDim.x + threadIdx.x;
    if (i < TOT3) d_cnt[i] = 0;
}

__global__ void csr_hist(const int* __restrict__ dst, int E, int rbase) {
    int e = blockIdx.x*blockDim.x + threadIdx.x;
    if (e < E) atomicAdd(&d_cnt[rbase + dst[e]], 1);
}

__global__ void scan_blocks() {                 // grid 147, block 1024
    __shared__ int buf[1024];
    int t = threadIdx.x, g = blockIdx.x*1024 + t;
    int v = (g < TOT3) ? d_cnt[g] : 0;
    buf[t] = v;
    __syncthreads();
    #pragma unroll
    for (int s = 1; s < 1024; s <<= 1) {
        int x = (t >= s) ? buf[t-s] : 0;
        __syncthreads();
        buf[t] += x;
        __syncthreads();
    }
    if (g < TOT3) d_off[g] = buf[t] - v;        // local exclusive
    if (t == 1023) d_part[blockIdx.x] = buf[1023];
}

__global__ void scan_part(int nb) {             // 1 block, 256 threads
    __shared__ int buf[256];
    int t = threadIdx.x;
    int v = (t < nb) ? d_part[t] : 0;
    buf[t] = v;
    __syncthreads();
    #pragma unroll
    for (int s = 1; s < 256; s <<= 1) {
        int x = (t >= s) ? buf[t-s] : 0;
        __syncthreads();
        buf[t] += x;
        __syncthreads();
    }
    if (t < nb) d_part[t] = buf[t] - v;         // exclusive
}

__global__ void scan_add() {                    // grid 147, block 1024
    int g = blockIdx.x*1024 + threadIdx.x;
    if (g >= TOT3) return;
    int o = d_off[g] + d_part[blockIdx.x];
    d_off[g] = o;
    d_cur[g] = o;
    if (g == TOT3-1) d_off[TOT3] = o + d_cnt[g];
}

__global__ void csr_fill(const int* __restrict__ src, const int* __restrict__ dst,
                         int E, int rbase) {
    int e = blockIdx.x*blockDim.x + threadIdx.x;
    if (e >= E) return;
    int pos = atomicAdd(&d_cur[rbase + dst[e]], 1);
    d_csrsrc[pos] = src[e];
}

// ---------------- fs via HMMA: fsh[r][m][n] = xh @ Whp^T ----------------------
// grid (ceil(NN/128), 12): blockIdx.y = r*4 + n-chunk(64). Block 256 = 8 warps,
// warp w computes rows m0+w*16 .. +15 for its 64-col chunk. All operands loaded
// directly from global (B chunk is 8KB, L1-resident; A rows held in registers).
__global__ void fs_hmma() {
    int w = threadIdx.x >> 5, lane = threadIdx.x & 31;
    int g = lane >> 2, tg = lane & 3;
    int r = blockIdx.y >> 2;
    int nbase = (blockIdx.y & 3) * 64;
    int m0 = blockIdx.x*128 + w*16;
    int r0 = m0 + g, r1 = m0 + g + 8;
    bool v0 = r0 < NN, v1 = r1 < NN;

    unsigned a[4][4];
    const __half* A0 = &d_xh[(size_t)(v0 ? r0 : 0)*DH];
    const __half* A1 = &d_xh[(size_t)(v1 ? r1 : 0)*DH];
    #pragma unroll
    for (int ks = 0; ks < 4; ks++) {
        int c0 = ks*16 + tg*2, c1 = c0 + 8;
        a[ks][0] = v0 ? *(const unsigned*)&A0[c0] : 0u;
        a[ks][1] = v1 ? *(const unsigned*)&A1[c0] : 0u;
        a[ks][2] = v0 ? *(const unsigned*)&A0[c1] : 0u;
        a[ks][3] = v1 ? *(const unsigned*)&A1[c1] : 0u;
    }

    const __half* Bp = &d_Whp[((size_t)r*FF + nbase)*DH];
    #pragma unroll
    for (int nc = 0; nc < 8; nc++) {
        const __half* Bn = &Bp[(size_t)(nc*8 + g)*DH];
        float c0 = 0.f, c1 = 0.f, c2 = 0.f, c3 = 0.f;
        #pragma unroll
        for (int ks = 0; ks < 4; ks++) {
            unsigned b0 = *(const unsigned*)&Bn[ks*16 + tg*2];
            unsigned b1 = *(const unsigned*)&Bn[ks*16 + tg*2 + 8];
            asm volatile(
                "mma.sync.aligned.m16n8k16.row.col.f32.f16.f16.f32 "
                "{%0,%1,%2,%3}, {%4,%5,%6,%7}, {%8,%9}, {%0,%1,%2,%3};"
                : "+f"(c0), "+f"(c1), "+f"(c2), "+f"(c3)
                : "r"(a[ks][0]), "r"(a[ks][1]), "r"(a[ks][2]), "r"(a[ks][3]),
                  "r"(b0), "r"(b1));
        }
        int col = nbase + nc*8 + tg*2;
        if (v0) *(unsigned*)&d_fsh[((size_t)r*NN + r0)*FF + col] = hpack(c0, c1);
        if (v1) *(unsigned*)&d_fsh[((size_t)r*NN + r1)*FF + col] = hpack(c2, c3);
    }
}

// ---------------- GEMM Nn=64: C = A[M,64] @ B[64,64] (+bias)(+relu) ----------
template<bool RELU, bool BIAS>
__global__ void gemm64(const float* __restrict__ A, const float* __restrict__ B,
                       float* __restrict__ C, const float* __restrict__ bias) {
    __shared__ float As[64][68];
    __shared__ float Bs[64][68];
    int m0 = blockIdx.x * 64;
    int t = threadIdx.x;

    #pragma unroll
    for (int l = 0; l < 4; l++) {
        int lin = t + l*256;
        int row = lin >> 4, c4 = lin & 15;
        float4 v = make_float4(0.f,0.f,0.f,0.f);
        if (m0 + row < NN) v = *(const float4*)&A[(size_t)(m0+row)*64 + c4*4];
        *(float4*)&As[row][c4*4] = v;
        float4 w = *(const float4*)&B[(size_t)row*64 + c4*4];
        *(float4*)&Bs[row][c4*4] = w;
    }
    __syncthreads();

    int ty = t >> 4, tx = t & 15;
    unsigned long long acc[4][2] = {};
    #pragma unroll
    for (int k = 0; k < 64; k++) {
        unsigned long long b01 = *(const unsigned long long*)&Bs[k][tx*4];
        unsigned long long b23 = *(const unsigned long long*)&Bs[k][tx*4+2];
        #pragma unroll
        for (int i = 0; i < 4; i++) {
            float a = As[ty*4+i][k];
            unsigned long long aa = pack2(a, a);
            ffma2(acc[i][0], aa, b01);
            ffma2(acc[i][1], aa, b23);
        }
    }

    #pragma unroll
    for (int i = 0; i < 4; i++) {
        int m = m0 + ty*4 + i;
        if (m >= NN) continue;
        float2 lo = unpack2(acc[i][0]), hi = unpack2(acc[i][1]);
        float4 o = make_float4(lo.x, lo.y, hi.x, hi.y);
        if (BIAS) {
            o.x += bias[tx*4+0]; o.y += bias[tx*4+1];
            o.z += bias[tx*4+2]; o.w += bias[tx*4+3];
        }
        if (RELU) {
            o.x = fmaxf(o.x, 0.f); o.y = fmaxf(o.y, 0.f);
            o.z = fmaxf(o.z, 0.f); o.w = fmaxf(o.w, 0.f);
        }
        *(float4*)&C[(size_t)m*64 + tx*4] = o;
    }
}

// ---------------- el/er for all 3 relations: [el|er] = xb @ Walr -------------
__global__ void elr_gemm() {          // block 768 threads, 32 nodes per block
    __shared__ float sW[64*24];
    __shared__ float sx[32*68];
    int t = threadIdx.x;
    for (int i = t; i < 1536; i += 768) {         // remap [r][k][c] -> [k][r*8+c]
        int r = i >> 9, k = (i >> 3) & 63, c = i & 7;
        sW[k*24 + r*8 + c] = d_Walr[i];
    }
    int n0 = blockIdx.x * 32;
    for (int i = t; i < 512; i += 768) {
        int row = i >> 4, c4 = i & 15;
        float4 v = make_float4(0.f,0.f,0.f,0.f);
        if (n0 + row < NN) v = ((const float4*)&d_xb[(size_t)(n0+row)*64])[c4];
        *(float4*)&sx[row*68 + c4*4] = v;
    }
    __syncthreads();
    int row = t / 24, col = t - row*24;
    if (row >= 32) return;
    int n = n0 + row;
    if (n >= NN) return;
    float sum = 0.f;
    #pragma unroll
    for (int k = 0; k < 64; k++) sum += sx[row*68 + k] * sW[k*24 + col];
    int r = col >> 3, c = col & 7, h = c & 3;
    if (c < 4) d_el[((size_t)r*NN + n)*4 + h] = sum;
    else       d_er[((size_t)r*NN + n)*4 + h] = sum;
}

// ---------------- fused gather-aggregate: ALL 3 relations per warp ------------
__device__ __forceinline__ float expleaky(float e) {
    e = (e >= 0.f) ? e : 0.2f*e;
    return __expf(e);
}

__global__ void aggregate3() {
    int d = (blockIdx.x*blockDim.x + threadIdx.x) >> 5;
    int lane = threadIdx.x & 31;
    if (d >= NN) return;
    int h = lane >> 3;
    float4 ta = make_float4(0.f,0.f,0.f,0.f);
    float4 tb = make_float4(0.f,0.f,0.f,0.f);

    #pragma unroll
    for (int r = 0; r < 3; r++) {
        int base = r*NN + d;
        int j0 = d_off[base], j1 = d_off[base+1];
        if (j0 == j1) continue;
        float erh = d_er[((size_t)r*NN + d)*4 + h];
        const float* el = &d_el[(size_t)r*NN*4];
        const __half* fsh = &d_fsh[(size_t)r*NN*FF];
        float4 a = make_float4(0.f,0.f,0.f,0.f);
        float4 b = make_float4(0.f,0.f,0.f,0.f);
        float ssum = 0.f;
        int j = j0;
        for (; j + 4 <= j1; j += 4) {
            int s0 = d_csrsrc[j], s1 = d_csrsrc[j+1], s2 = d_csrsrc[j+2], s3 = d_csrsrc[j+3];
            float e0 = el[s0*4+h] + erh, e1 = el[s1*4+h] + erh;
            float e2 = el[s2*4+h] + erh, e3 = el[s3*4+h] + erh;
            uint4 v0 = *(const uint4*)&fsh[(size_t)s0*FF + lane*8];
            uint4 v1 = *(const uint4*)&fsh[(size_t)s1*FF + lane*8];
            uint4 v2 = *(const uint4*)&fsh[(size_t)s2*FF + lane*8];
            uint4 v3 = *(const uint4*)&fsh[(size_t)s3*FF + lane*8];
            e0 = expleaky(e0); e1 = expleaky(e1); e2 = expleaky(e2); e3 = expleaky(e3);
            ssum += (e0 + e1) + (e2 + e3);
            {
                float2 p0 = hunpack(v0.x), p1 = hunpack(v1.x), p2 = hunpack(v2.x), p3 = hunpack(v3.x);
                a.x += e0*p0.x + e1*p1.x + e2*p2.x + e3*p3.x;
                a.y += e0*p0.y + e1*p1.y + e2*p2.y + e3*p3.y;
            }
            {
                float2 p0 = hunpack(v0.y), p1 = hunpack(v1.y), p2 = hunpack(v2.y), p3 = hunpack(v3.y);
                a.z += e0*p0.x + e1*p1.x + e2*p2.x + e3*p3.x;
                a.w += e0*p0.y + e1*p1.y + e2*p2.y + e3*p3.y;
            }
            {
                float2 p0 = hunpack(v0.z), p1 = hunpack(v1.z), p2 = hunpack(v2.z), p3 = hunpack(v3.z);
                b.x += e0*p0.x + e1*p1.x + e2*p2.x + e3*p3.x;
                b.y += e0*p0.y + e1*p1.y + e2*p2.y + e3*p3.y;
            }
            {
                float2 p0 = hunpack(v0.w), p1 = hunpack(v1.w), p2 = hunpack(v2.w), p3 = hunpack(v3.w);
                b.z += e0*p0.x + e1*p1.x + e2*p2.x + e3*p3.x;
                b.w += e0*p0.y + e1*p1.y + e2*p2.y + e3*p3.y;
            }
        }
        for (; j < j1; j++) {
            int s = d_csrsrc[j];
            float e = expleaky(el[s*4+h] + erh);
            ssum += e;
            uint4 v = *(const uint4*)&fsh[(size_t)s*FF + lane*8];
            float2 p0 = hunpack(v.x), p1 = hunpack(v.y), p2 = hunpack(v.z), p3 = hunpack(v.w);
            a.x += e*p0.x; a.y += e*p0.y;
            a.z += e*p1.x; a.w += e*p1.y;
            b.x += e*p2.x; b.y += e*p2.y;
            b.z += e*p3.x; b.w += e*p3.y;
        }
        float w = 0.25f * __frcp_rn(ssum);
        ta.x += w*a.x; ta.y += w*a.y; ta.z += w*a.z; ta.w += w*a.w;
        tb.x += w*b.x; tb.y += w*b.y; tb.z += w*b.z; tb.w += w*b.w;
    }

    #pragma unroll
    for (int m = 8; m <= 16; m <<= 1) {
        ta.x += __shfl_xor_sync(0xffffffffu, ta.x, m);
        ta.y += __shfl_xor_sync(0xffffffffu, ta.y, m);
        ta.z += __shfl_xor_sync(0xffffffffu, ta.z, m);
        ta.w += __shfl_xor_sync(0xffffffffu, ta.w, m);
        tb.x += __shfl_xor_sync(0xffffffffu, tb.x, m);
        tb.y += __shfl_xor_sync(0xffffffffu, tb.y, m);
        tb.z += __shfl_xor_sync(0xffffffffu, tb.z, m);
        tb.w += __shfl_xor_sync(0xffffffffu, tb.w, m);
    }
    if (lane < 8) {
        float* xp = &d_xm[(size_t)d*DH + lane*8];
        float4 o0 = ((float4*)xp)[0];
        float4 o1 = ((float4*)xp)[1];
        o0.x += ta.x; o0.y += ta.y; o0.z += ta.z; o0.w += ta.w;
        o1.x += tb.x; o1.y += tb.y; o1.z += tb.z; o1.w += tb.w;
        ((float4*)xp)[0] = o0;
        ((float4*)xp)[1] = o1;
    }
}

// ---------------- launch -----------------------------------------------------
extern "C" void kernel_launch(void* const* d_in, const int* in_sizes, int n_in,
                              void* d_out, int out_size) {
    const float* x0 = (const float*)d_in[0];
    const int* srcs[3] = {(const int*)d_in[1], (const int*)d_in[3], (const int*)d_in[5]};
    const int* dsts[3] = {(const int*)d_in[2], (const int*)d_in[4], (const int*)d_in[6]};
    int Es[3] = { in_sizes[1], in_sizes[3], in_sizes[5] };
    const float* Wl[2]   = {(const float*)d_in[7],  (const float*)d_in[12]};
    const float* all_[2] = {(const float*)d_in[8],  (const float*)d_in[13]};
    const float* arl[2]  = {(const float*)d_in[9],  (const float*)d_in[14]};
    const float* bl[2]   = {(const float*)d_in[10], (const float*)d_in[15]};
    const float* rWl[2]  = {(const float*)d_in[11], (const float*)d_in[16]};
    const float* fcWl[2] = {(const float*)d_in[17], (const float*)d_in[19]};
    const float* fcbl[2] = {(const float*)d_in[18], (const float*)d_in[20]};
    const float* gl[2]   = {(const float*)d_in[21], (const float*)d_in[23]};
    const float* bel[2]  = {(const float*)d_in[22], (const float*)d_in[24]};

    float *p_xb, *p_xm, *p_x1, *p_rWfold, *p_bfold;
    cudaGetSymbolAddress((void**)&p_xb,     d_xb);
    cudaGetSymbolAddress((void**)&p_xm,     d_xm);
    cudaGetSymbolAddress((void**)&p_x1,     d_x1);
    cudaGetSymbolAddress((void**)&p_rWfold, d_rWfold);
    cudaGetSymbolAddress((void**)&p_bfold,  d_bfold);

    const int TPB = 256;
    const int NB_SCAN = (TOT3 + 1023) / 1024;   // 147

    // ---- CSR build (shared by both layers) ----
    csr_zero<<<(TOT3+TPB-1)/TPB, TPB>>>();
    for (int r = 0; r < 3; r++)
        csr_hist<<<(Es[r]+TPB-1)/TPB, TPB>>>(dsts[r], Es[r], r*NN);
    scan_blocks<<<NB_SCAN, 1024>>>();
    scan_part<<<1, 256>>>(NB_SCAN);
    scan_add<<<NB_SCAN, 1024>>>();
    for (int r = 0; r < 3; r++)
        csr_fill<<<(Es[r]+TPB-1)/TPB, TPB>>>(srcs[r], dsts[r], Es[r], r*NN);

    dim3 ghm((NN + 127)/128, 12);
    for (int L = 0; L < 2; L++) {
        const float* xin = (L == 0) ? x0 : p_x1;
        float* xout = (L == 0) ? p_x1 : (float*)d_out;

        bn_stats_init<<<1, 64>>>();
        bn_reduce<<<256, 256>>>(xin);
        bn_apply<<<(NN*DH + TPB-1)/TPB, TPB>>>(xin, gl[L], bel[L]);

        prep_rwfold<<<(DH*DH + TPB-1)/TPB, TPB>>>(rWl[L], bl[L]);
        prep_walr<<<(3*DH*8 + TPB-1)/TPB, TPB>>>(Wl[L], all_[L], arl[L]);
        wh_prep<<<(3*FF*DH + TPB-1)/TPB, TPB>>>(Wl[L]);

        // residual (+bias, head-mean folded): xm = xb @ rWfold + bfold
        gemm64<false,true><<<(NN+63)/64, 256>>>(p_xb, p_rWfold, p_xm, p_bfold);

        elr_gemm<<<(NN+31)/32, 768>>>();
        fs_hmma<<<ghm, 256>>>();
        aggregate3<<<(NN*32 + TPB-1)/TPB, TPB>>>();

        // fc + relu
        gemm64<true,true><<<(NN+63)/64, 256>>>(p_xm, fcWl[L], xout, fcbl[L]);
    }
}